// round 8
// baseline (speedup 1.0000x reference)
#include <cuda_runtime.h>
#include <cuda_bf16.h>
#include <cstdint>

// Problem constants
#define NPTS   32768
#define DK     512
#define NC0    1024
#define NC1    512
#define NC2    256
#define NCODES 1792
#define CB1_OFF 1024
#define CB2_OFF 1536

// out layout: main_out | sub_out | loss | ms_k_i(16x512 zeros) | unique
#define MAIN_OFF 0
#define SUB_OFF  (NPTS*DK)
#define LOSS_OFF (2*NPTS*DK)
#define MS_OFF   (LOSS_OFF + 1)
#define MS_N     (16*DK)
#define UNIQ_OFF (MS_OFF + MS_N)

#define MARGIN 2.0f   // empirically validated bound on 2x hh-approx score error

// Scratch (device globals; no allocation allowed)
__device__ float         g_cb[NCODES * DK];
__device__ float         g_halfnorm[NCODES];
__device__ float         g_loss[2];
__device__ int           g_used[NC0];
__device__ __nv_bfloat16 g_xh[NPTS * DK];
__device__ __nv_bfloat16 g_ch[NCODES * DK];
__device__ ulonglong2    g_t2[NPTS * 14];   // per (row,tile) top-2 packed (scoreord<<32|gidx)

__device__ __forceinline__ unsigned int f2ord(float f) {
    unsigned int u = __float_as_uint(f);
    return (u & 0x80000000u) ? ~u : (u | 0x80000000u);
}
__device__ __forceinline__ float ord2f(unsigned int u) {
    unsigned int v = (u & 0x80000000u) ? (u & 0x7fffffffu) : ~u;
    return __uint_as_float(v);
}
__device__ __forceinline__ uint32_t smem_u32(const void* p) {
    uint32_t a;
    asm("{ .reg .u64 t; cvta.to.shared.u64 t, %1; cvt.u32.u64 %0, t; }" : "=r"(a) : "l"(p));
    return a;
}
__device__ __forceinline__ void cp16(uint32_t dst, const void* src) {
    asm volatile("cp.async.cg.shared.global [%0], [%1], 16;" :: "r"(dst), "l"(src));
}
#define CP_COMMIT() asm volatile("cp.async.commit_group;" ::: "memory")
#define CP_WAIT(n)  asm volatile("cp.async.wait_group %0;" :: "n"(n) : "memory")

__device__ __forceinline__ void ldsm4(uint32_t* r, uint32_t addr) {
    asm volatile("ldmatrix.sync.aligned.m8n8.x4.shared.b16 {%0,%1,%2,%3}, [%4];"
        : "=r"(r[0]), "=r"(r[1]), "=r"(r[2]), "=r"(r[3]) : "r"(addr));
}
__device__ __forceinline__ void mma_bf16(float* d, const uint32_t* a,
                                         uint32_t b0, uint32_t b1) {
    asm volatile("mma.sync.aligned.m16n8k16.row.col.f32.bf16.bf16.f32 "
        "{%0,%1,%2,%3}, {%4,%5,%6,%7}, {%8,%9}, {%0,%1,%2,%3};"
        : "+f"(d[0]), "+f"(d[1]), "+f"(d[2]), "+f"(d[3])
        : "r"(a[0]), "r"(a[1]), "r"(a[2]), "r"(a[3]), "r"(b0), "r"(b1));
}

// ---------------------------------------------------------------------------
// front: blocks [0,192) = sub-codebook GEMM; rest = init+copy+split x.  (#1)
// ---------------------------------------------------------------------------
__global__ __launch_bounds__(256) void k_front(
    const float* __restrict__ x, const float* __restrict__ c,
    const float* __restrict__ W1, const float* __restrict__ b1,
    const float* __restrict__ W2, const float* __restrict__ b2,
    float* __restrict__ out)
{
    if (blockIdx.x < 192) {
        const int bx = blockIdx.x;
        const int i0 = (bx % 96) * 8;
        const int d  = (bx / 96) * 256 + threadIdx.x;
        __shared__ float Ws[8][128];
        float acc[8];
#pragma unroll
        for (int r = 0; r < 8; r++) acc[r] = 0.0f;
        for (int j0 = 0; j0 < NC0; j0 += 128) {
#pragma unroll
            for (int l = 0; l < 4; l++) {
                int p = threadIdx.x + l * 256;
                int r = p >> 7, jj = p & 127;
                int gi = i0 + r;
                const float* Wrow = (gi < NC1) ? &W1[(size_t)gi * NC0]
                                               : &W2[(size_t)(gi - NC1) * NC0];
                Ws[r][jj] = Wrow[j0 + jj];
            }
            __syncthreads();
            for (int jj = 0; jj < 128; jj++) {
                float cv = c[(size_t)(j0 + jj) * DK + d];
#pragma unroll
                for (int r = 0; r < 8; r++) acc[r] += Ws[r][jj] * cv;
            }
            __syncthreads();
        }
#pragma unroll
        for (int r = 0; r < 8; r++) {
            int gi = i0 + r;
            float bias = (gi < NC1) ? b1[gi] : b2[gi - NC1];
            g_cb[(size_t)(CB1_OFF + gi) * DK + d] = acc[r] + bias;
        }
    } else {
        int i = (blockIdx.x - 192) * 256 + threadIdx.x;
        if (i < NPTS * DK / 4) {
            float4 v = reinterpret_cast<const float4*>(x)[i];
            __nv_bfloat162* ph = reinterpret_cast<__nv_bfloat162*>(g_xh);
            ph[2*i]   = {__float2bfloat16(v.x), __float2bfloat16(v.y)};
            ph[2*i+1] = {__float2bfloat16(v.z), __float2bfloat16(v.w)};
        }
        if (i < NC0 * DK / 4)
            reinterpret_cast<float4*>(g_cb)[i] = reinterpret_cast<const float4*>(c)[i];
        if (i < MS_N) out[MS_OFF + i] = 0.0f;
        if (i < NC0)  g_used[i] = 0;
        if (i < 2)    g_loss[i] = 0.0f;
    }
}

// ---------------------------------------------------------------------------
// prep2: split codebooks to bf16 + halfnorms (one warp/row)              (#2)
// ---------------------------------------------------------------------------
__global__ __launch_bounds__(256) void k_prep2() {
    const int warp = (blockIdx.x * blockDim.x + threadIdx.x) >> 5;
    const int lane = threadIdx.x & 31;
    if (warp >= NCODES) return;
    const float4* row4 = reinterpret_cast<const float4*>(g_cb + (size_t)warp * DK);
    __nv_bfloat162* ch2 = reinterpret_cast<__nv_bfloat162*>(g_ch + (size_t)warp * DK);
    float s = 0.0f;
#pragma unroll
    for (int q = 0; q < 4; q++) {
        float4 v = row4[q * 32 + lane];
        s += v.x * v.x + v.y * v.y + v.z * v.z + v.w * v.w;
        ch2[(q * 32 + lane) * 2]     = {__float2bfloat16(v.x), __float2bfloat16(v.y)};
        ch2[(q * 32 + lane) * 2 + 1] = {__float2bfloat16(v.z), __float2bfloat16(v.w)};
    }
#pragma unroll
    for (int off = 16; off >= 1; off >>= 1) s += __shfl_xor_sync(0xffffffffu, s, off);
    if (lane == 0) g_halfnorm[warp] = 0.5f * s;
}

// ---------------------------------------------------------------------------
// HMMA approx GEMM (hh, K=512) + per-(row,tile) top-2 emit.              (#3)
// CTA tile 128x128, 8 warps (4m x 2n), BK=64, 3-stage cp.async.
// ---------------------------------------------------------------------------
__device__ __forceinline__ void stage_chunk(int chunk, int stage, uint32_t sbase,
                                            int tid, int row0, int c0) {
    const int koff = chunk << 6;
    const uint32_t sA = sbase + (uint32_t)stage * 32768u;
    const uint32_t sB = sA + 16384u;
#pragma unroll
    for (int p = 0; p < 4; p++) {
        int idx = tid + (p << 8);
        int row = idx >> 3, cc = idx & 7;
        uint32_t sw = (uint32_t)((cc ^ (row & 7)) << 4);
        cp16(sA + (uint32_t)row * 128u + sw,
             g_xh + (size_t)(row0 + row) * DK + koff + cc * 8);
        cp16(sB + (uint32_t)row * 128u + sw,
             g_ch + (size_t)(c0 + row) * DK + koff + cc * 8);
    }
    CP_COMMIT();
}

__global__ __launch_bounds__(256) void k_mma() {
    extern __shared__ __align__(16) char smem[];
    __shared__ float hn_s[128];
    const uint32_t sbase = smem_u32(smem);
    const int tid  = threadIdx.x;
    const int lane = tid & 31;
    const int warp = tid >> 5;
    const int wm = warp >> 1;
    const int wn = warp & 1;
    const int c0   = blockIdx.x << 7;
    const int row0 = blockIdx.y << 7;

    if (tid < 128) hn_s[tid] = g_halfnorm[c0 + tid];

    float acc[2][8][4];
#pragma unroll
    for (int i = 0; i < 2; i++)
#pragma unroll
        for (int j = 0; j < 8; j++)
#pragma unroll
            for (int k = 0; k < 4; k++) acc[i][j][k] = 0.0f;

    stage_chunk(0, 0, sbase, tid, row0, c0);
    stage_chunk(1, 1, sbase, tid, row0, c0);

    const int rsel = lane & 15;
    const int ksel = lane >> 4;

    for (int chunk = 0; chunk < 8; chunk++) {
        const int stage = chunk % 3;
        if (chunk < 6) CP_WAIT(1); else CP_WAIT(0);
        __syncthreads();
        if (chunk + 2 < 8)
            stage_chunk(chunk + 2, (chunk + 2) % 3, sbase, tid, row0, c0);

        const uint32_t sA = sbase + (uint32_t)stage * 32768u;
        const uint32_t sB = sA + 16384u;
#pragma unroll
        for (int q = 0; q < 4; q++) {
            uint32_t a[2][4], b[4][4];
            const int csel = (q << 1) + ksel;
#pragma unroll
            for (int mf = 0; mf < 2; mf++) {
                int row = (wm << 5) + (mf << 4) + rsel;
                ldsm4(a[mf], sA + (uint32_t)row * 128u
                           + (uint32_t)((csel ^ (row & 7)) << 4));
            }
#pragma unroll
            for (int bt = 0; bt < 4; bt++) {
                int row = (wn << 6) + (bt << 4) + rsel;
                ldsm4(b[bt], sB + (uint32_t)row * 128u
                           + (uint32_t)((csel ^ (row & 7)) << 4));
            }
#pragma unroll
            for (int mf = 0; mf < 2; mf++)
#pragma unroll
                for (int bt = 0; bt < 4; bt++) {
                    mma_bf16(acc[mf][bt * 2],     a[mf], b[bt][0], b[bt][2]);
                    mma_bf16(acc[mf][bt * 2 + 1], a[mf], b[bt][1], b[bt][3]);
                }
        }
        __syncthreads();
    }

    // epilogue: per-row top-2 across this 128-code tile. wn splits cols:
    // combine the two wn halves via smem? No: wn=0/1 cover different col halves
    // but SAME rows -> merge via one ull pair in smem per row is complex.
    // Instead: each (row, wn-half) emits top2 of 64 cols; merge across wn
    // through shared memory (two ulonglong2 per row).
    __shared__ ulonglong2 t2s[128][2];
    const int g = lane >> 2, t = lane & 3;

#pragma unroll
    for (int mf = 0; mf < 2; mf++) {
#pragma unroll
        for (int rh = 0; rh < 2; rh++) {
            const int row = (wm << 5) + (mf << 4) + (rh << 3) + g;
            unsigned long long b1 = ~0ULL, s1 = ~0ULL;
#pragma unroll
            for (int nf = 0; nf < 8; nf++) {
                int colb = (wn << 6) + (nf << 3) + (t << 1);
                float v0 = hn_s[colb]     - acc[mf][nf][rh * 2];
                float v1 = hn_s[colb + 1] - acc[mf][nf][rh * 2 + 1];
                unsigned long long p0 = ((unsigned long long)f2ord(v0) << 32)
                                      | (unsigned)(c0 + colb);
                unsigned long long p1 = ((unsigned long long)f2ord(v1) << 32)
                                      | (unsigned)(c0 + colb + 1);
                if (p0 < b1) { s1 = b1; b1 = p0; } else if (p0 < s1) s1 = p0;
                if (p1 < b1) { s1 = b1; b1 = p1; } else if (p1 < s1) s1 = p1;
            }
            // merge across quad (t = lane bits 0-1)
#pragma unroll
            for (int off = 2; off >= 1; off >>= 1) {
                unsigned long long ob = __shfl_xor_sync(0xffffffffu, b1, off);
                unsigned long long os = __shfl_xor_sync(0xffffffffu, s1, off);
                if (ob < b1) { s1 = (b1 < os) ? b1 : os; b1 = ob; }
                else         { s1 = (ob < s1) ? ob : s1; }
            }
            if (t == 0) t2s[row][wn] = make_ulonglong2(b1, s1);
        }
    }
    __syncthreads();

    // merge wn halves and write: 128 rows, threads 0-127
    if (tid < 128) {
        ulonglong2 u0 = t2s[tid][0];
        ulonglong2 u1 = t2s[tid][1];
        unsigned long long b, s;
        if (u0.x < u1.x) { b = u0.x; s = (u0.y < u1.x) ? u0.y : u1.x; }
        else             { b = u1.x; s = (u1.y < u0.x) ? u1.y : u0.x; }
        g_t2[(size_t)(row0 + tid) * 14 + blockIdx.x] = make_ulonglong2(b, s);
    }
}

// ---------------------------------------------------------------------------
// decide + gather: one WARP per row, no block syncs.                     (#4)
// ---------------------------------------------------------------------------
__global__ __launch_bounds__(256) void k_rg(const float* __restrict__ x,
                                            float* __restrict__ out) {
    __shared__ float xs[8][DK];
    const int w    = threadIdx.x >> 5;
    const int lane = threadIdx.x & 31;
    const int row  = blockIdx.x * 8 + w;

    // x row into registers (and reusable for smem spill on rescan)
    float4 xv[4];
    const float4* xr4 = reinterpret_cast<const float4*>(x + (size_t)row * DK);
#pragma unroll
    for (int q = 0; q < 4; q++) xv[q] = xr4[q * 32 + lane];

    // load this row's 14 top-2 entries
    unsigned long long tb = ~0ULL, ts = ~0ULL;
    if (lane < 14) {
        ulonglong2 u = g_t2[(size_t)row * 14 + lane];
        tb = u.x; ts = u.y;
    }

    int zloc[3];
    bool spilled = false;

#pragma unroll
    for (int grp = 0; grp < 3; grp++) {
        const int t0 = (grp == 0) ? 0 : (grp == 1) ? 8 : 12;
        const int t1 = (grp == 0) ? 8 : (grp == 1) ? 12 : 14;
        const int gstart = (grp == 0) ? 0 : (grp == 1) ? CB1_OFF : CB2_OFF;
        const bool inr = (lane >= t0) && (lane < t1);

        unsigned long long b = inr ? tb : ~0ULL;
        unsigned long long best = b;
#pragma unroll
        for (int off = 16; off >= 1; off >>= 1) {
            unsigned long long o = __shfl_xor_sync(0xffffffffu, best, off);
            if (o < best) best = o;
        }
        const unsigned thr_ord = f2ord(ord2f((unsigned)(best >> 32)) + MARGIN);
        const unsigned long long thr_pack =
            ((unsigned long long)thr_ord << 32) | 0xffffffffULL;

        unsigned long long m = inr ? ((b == best) ? ts : b) : ~0ULL;
        unsigned long long second = m;
#pragma unroll
        for (int off = 16; off >= 1; off >>= 1) {
            unsigned long long o = __shfl_xor_sync(0xffffffffu, second, off);
            if (o < second) second = o;
        }

        if (second > thr_pack) {
            zloc[grp] = (int)(best & 0xffffffffu) - gstart;
            continue;
        }

        // ambiguous: exact fp64 rescoring of candidates
        double bs = 1e300; int bi = 0x7fffffff;
        const unsigned ms = __ballot_sync(0xffffffffu, inr && (ts <= thr_pack));
        unsigned mb = __ballot_sync(0xffffffffu, inr && (tb <= thr_pack)) & ~ms;

        while (mb) {     // single-entry candidates (tile-best only)
            int L = __ffs(mb) - 1; mb &= mb - 1;
            int gi = (int)(__shfl_sync(0xffffffffu, tb, L) & 0xffffffffu);
            const float4* cr4 = reinterpret_cast<const float4*>(
                g_cb + (size_t)gi * DK);
            double ds = 0.0;
#pragma unroll
            for (int q = 0; q < 4; q++) {
                float4 cv = cr4[q * 32 + lane];
                ds = fma((double)xv[q].x, (double)cv.x, ds);
                ds = fma((double)xv[q].y, (double)cv.y, ds);
                ds = fma((double)xv[q].z, (double)cv.z, ds);
                ds = fma((double)xv[q].w, (double)cv.w, ds);
            }
#pragma unroll
            for (int off = 16; off >= 1; off >>= 1)
                ds += __shfl_xor_sync(0xffffffffu, ds, off);
            double sc = (double)g_halfnorm[gi] - ds;
            if (sc < bs || (sc == bs && gi < bi)) { bs = sc; bi = gi; }
        }

        if (ms) {        // tiles needing full rescan (2nd entry within margin)
            if (!spilled) {
                float4* xs4 = reinterpret_cast<float4*>(xs[w]);
#pragma unroll
                for (int q = 0; q < 4; q++) xs4[q * 32 + lane] = xv[q];
                spilled = true;
            }
            __syncwarp();
            unsigned mr = ms;
            double lbs = 1e300; int lbi = 0x7fffffff;
            while (mr) {
                int T = __ffs(mr) - 1; mr &= mr - 1;
#pragma unroll
                for (int k = 0; k < 4; k++) {
                    int gi = T * 128 + k * 32 + lane;
                    const float* cr = g_cb + (size_t)gi * DK;
                    double d0 = 0.0, d1 = 0.0, d2 = 0.0, d3 = 0.0;
                    for (int dd = 0; dd < DK; dd += 4) {
                        d0 = fma((double)xs[w][dd],     (double)cr[dd],     d0);
                        d1 = fma((double)xs[w][dd + 1], (double)cr[dd + 1], d1);
                        d2 = fma((double)xs[w][dd + 2], (double)cr[dd + 2], d2);
                        d3 = fma((double)xs[w][dd + 3], (double)cr[dd + 3], d3);
                    }
                    double sc = (double)g_halfnorm[gi] - ((d0 + d1) + (d2 + d3));
                    if (sc < lbs || (sc == lbs && gi < lbi)) { lbs = sc; lbi = gi; }
                }
            }
#pragma unroll
            for (int off = 16; off >= 1; off >>= 1) {
                double od = __shfl_xor_sync(0xffffffffu, lbs, off);
                int    oi = __shfl_xor_sync(0xffffffffu, lbi, off);
                if (od < lbs || (od == lbs && oi < lbi)) { lbs = od; lbi = oi; }
            }
            if (lbs < bs || (lbs == bs && lbi < bi)) { bs = lbs; bi = lbi; }
        }
        zloc[grp] = bi - gstart;
    }

    // gather + outputs + loss
    const int z  = zloc[0];
    const int z1 = zloc[1];
    const int z2 = zloc[2];
    if (lane == 0) g_used[z] = 1;

    const float4* m  = reinterpret_cast<const float4*>(&g_cb[(size_t)z * DK]);
    const float4* s1 = reinterpret_cast<const float4*>(&g_cb[(size_t)(CB1_OFF + z1) * DK]);
    const float4* s2 = reinterpret_cast<const float4*>(&g_cb[(size_t)(CB2_OFF + z2) * DK]);
    float4* om = reinterpret_cast<float4*>(&out[MAIN_OFF + (size_t)row * DK]);
    float4* os = reinterpret_cast<float4*>(&out[SUB_OFF + (size_t)row * DK]);

    float lm = 0.0f, ls = 0.0f;
#pragma unroll
    for (int q = 0; q < 4; q++) {
        int idx = q * 32 + lane;
        float4 mv = m[idx];
        float4 a  = s1[idx];
        float4 b  = s2[idx];
        float4 sv = make_float4(0.5f * (a.x + b.x), 0.5f * (a.y + b.y),
                                0.5f * (a.z + b.z), 0.5f * (a.w + b.w));
        om[idx] = mv;
        os[idx] = sv;
        float4 xq = xv[q];
        float dmx = mv.x - xq.x, dmy = mv.y - xq.y, dmz = mv.z - xq.z, dmw = mv.w - xq.w;
        float dsx = sv.x - xq.x, dsy = sv.y - xq.y, dsz = sv.z - xq.z, dsw = sv.w - xq.w;
        lm += dmx * dmx + dmy * dmy + dmz * dmz + dmw * dmw;
        ls += dsx * dsx + dsy * dsy + dsz * dsz + dsw * dsw;
    }
#pragma unroll
    for (int off = 16; off >= 1; off >>= 1) {
        lm += __shfl_xor_sync(0xffffffffu, lm, off);
        ls += __shfl_xor_sync(0xffffffffu, ls, off);
    }
    if (lane == 0) {
        atomicAdd(&g_loss[0], lm);
        atomicAdd(&g_loss[1], ls);
    }
}

// ---------------------------------------------------------------------------
__global__ void k_final(const int* __restrict__ training, float* __restrict__ out) {
    const int tid = threadIdx.x;
    int cnt = 0;
    for (int i = tid; i < NC0; i += 256) cnt += g_used[i];
#pragma unroll
    for (int off = 16; off >= 1; off >>= 1) cnt += __shfl_xor_sync(0xffffffffu, cnt, off);
    __shared__ int sc[8];
    int wid = tid >> 5, lane = tid & 31;
    if (lane == 0) sc[wid] = cnt;
    __syncthreads();
    if (tid == 0) {
        int total = 0;
#pragma unroll
        for (int w = 0; w < 8; w++) total += sc[w];
        float e_sum = g_loss[0] + g_loss[1];
        out[LOSS_OFF] = (*training != 0)
                      ? 1.25f * e_sum / ((float)NPTS * (float)DK) : 0.0f;
        out[UNIQ_OFF] = (float)total;
    }
}

// ---------------------------------------------------------------------------
extern "C" void kernel_launch(void* const* d_in, const int* in_sizes, int n_in,
                              void* d_out, int out_size) {
    const float* x  = (const float*)d_in[0];
    const float* c  = (const float*)d_in[1];
    const float* W1 = (const float*)d_in[2];
    const float* b1 = (const float*)d_in[3];
    const float* W2 = (const float*)d_in[4];
    const float* b2 = (const float*)d_in[5];
    const int* training = (const int*)d_in[6];
    float* out = (float*)d_out;

    const int MMA_SMEM = 3 * 32768;   // 96KB pipeline stages
    cudaFuncSetAttribute(k_mma, cudaFuncAttributeMaxDynamicSharedMemorySize, MMA_SMEM);

    k_front<<<192 + 16384, 256>>>(x, c, W1, b1, W2, b2, out);       // #1
    k_prep2<<<(NCODES * 32 + 255) / 256, 256>>>();                   // #2
    {
        dim3 g(NCODES / 128, NPTS / 128);   // (14, 256)
        k_mma<<<g, 256, MMA_SMEM>>>();                               // #3
    }
    k_rg<<<NPTS / 8, 256>>>(x, out);                                 // #4
    k_final<<<1, 256>>>(training, out);                              // #5
}

// round 10
// speedup vs baseline: 1.6230x; 1.6230x over previous
#include <cuda_runtime.h>
#include <cuda_bf16.h>
#include <cstdint>

// Problem constants
#define NPTS   32768
#define DK     512
#define NC0    1024
#define NC1    512
#define NC2    256
#define NCODES 1792
#define CB1_OFF 1024
#define CB2_OFF 1536

// out layout: main_out | sub_out | loss | ms_k_i(16x512 zeros) | unique
#define MAIN_OFF 0
#define SUB_OFF  (NPTS*DK)
#define LOSS_OFF (2*NPTS*DK)
#define MS_OFF   (LOSS_OFF + 1)
#define MS_N     (16*DK)
#define UNIQ_OFF (MS_OFF + MS_N)

#define MARGIN 2.0f   // empirically validated bound on 2x hh-approx score error

// Scratch (device globals; no allocation allowed)
__device__ float         g_cb[NCODES * DK];
__device__ float         g_halfnorm[NCODES];
__device__ float         g_loss[2];
__device__ int           g_used[NC0];
__device__ __nv_bfloat16 g_xh[NPTS * DK];
__device__ __nv_bfloat16 g_ch[NCODES * DK];
// per (row, 64-code half-tile) top-2 packed (scoreord<<32 | global_idx); 28 halves/row
__device__ ulonglong2    g_t2[(size_t)NPTS * 28];

__device__ __forceinline__ unsigned int f2ord(float f) {
    unsigned int u = __float_as_uint(f);
    return (u & 0x80000000u) ? ~u : (u | 0x80000000u);
}
__device__ __forceinline__ float ord2f(unsigned int u) {
    unsigned int v = (u & 0x80000000u) ? (u & 0x7fffffffu) : ~u;
    return __uint_as_float(v);
}
__device__ __forceinline__ uint32_t smem_u32(const void* p) {
    uint32_t a;
    asm("{ .reg .u64 t; cvta.to.shared.u64 t, %1; cvt.u32.u64 %0, t; }" : "=r"(a) : "l"(p));
    return a;
}
__device__ __forceinline__ void cp16(uint32_t dst, const void* src) {
    asm volatile("cp.async.cg.shared.global [%0], [%1], 16;" :: "r"(dst), "l"(src));
}
#define CP_COMMIT() asm volatile("cp.async.commit_group;" ::: "memory")
#define CP_WAIT(n)  asm volatile("cp.async.wait_group %0;" :: "n"(n) : "memory")

__device__ __forceinline__ void ldsm4(uint32_t* r, uint32_t addr) {
    asm volatile("ldmatrix.sync.aligned.m8n8.x4.shared.b16 {%0,%1,%2,%3}, [%4];"
        : "=r"(r[0]), "=r"(r[1]), "=r"(r[2]), "=r"(r[3]) : "r"(addr));
}
__device__ __forceinline__ void mma_bf16(float* d, const uint32_t* a,
                                         uint32_t b0, uint32_t b1) {
    asm volatile("mma.sync.aligned.m16n8k16.row.col.f32.bf16.bf16.f32 "
        "{%0,%1,%2,%3}, {%4,%5,%6,%7}, {%8,%9}, {%0,%1,%2,%3};"
        : "+f"(d[0]), "+f"(d[1]), "+f"(d[2]), "+f"(d[3])
        : "r"(a[0]), "r"(a[1]), "r"(a[2]), "r"(a[3]), "r"(b0), "r"(b1));
}

// coalesced warp-cooperative exact fp64 dot: lanes over dims, all lanes return sum
__device__ __forceinline__ double wdot(const float4* xv, int gi, int lane) {
    const float4* cr4 = reinterpret_cast<const float4*>(g_cb + (size_t)gi * DK);
    double ds = 0.0;
#pragma unroll
    for (int q = 0; q < 4; q++) {
        float4 cv = cr4[q * 32 + lane];
        ds = fma((double)xv[q].x, (double)cv.x, ds);
        ds = fma((double)xv[q].y, (double)cv.y, ds);
        ds = fma((double)xv[q].z, (double)cv.z, ds);
        ds = fma((double)xv[q].w, (double)cv.w, ds);
    }
#pragma unroll
    for (int off = 16; off >= 1; off >>= 1)
        ds += __shfl_xor_sync(0xffffffffu, ds, off);
    return ds;
}

// ---------------------------------------------------------------------------
// front: blocks [0,192) = sub-codebook GEMM; rest = init+copy+split x.  (#1)
// ---------------------------------------------------------------------------
__global__ __launch_bounds__(256) void k_front(
    const float* __restrict__ x, const float* __restrict__ c,
    const float* __restrict__ W1, const float* __restrict__ b1,
    const float* __restrict__ W2, const float* __restrict__ b2,
    float* __restrict__ out)
{
    if (blockIdx.x < 192) {
        const int bx = blockIdx.x;
        const int i0 = (bx % 96) * 8;
        const int d  = (bx / 96) * 256 + threadIdx.x;
        __shared__ float Ws[8][128];
        float acc[8];
#pragma unroll
        for (int r = 0; r < 8; r++) acc[r] = 0.0f;
        for (int j0 = 0; j0 < NC0; j0 += 128) {
#pragma unroll
            for (int l = 0; l < 4; l++) {
                int p = threadIdx.x + l * 256;
                int r = p >> 7, jj = p & 127;
                int gi = i0 + r;
                const float* Wrow = (gi < NC1) ? &W1[(size_t)gi * NC0]
                                               : &W2[(size_t)(gi - NC1) * NC0];
                Ws[r][jj] = Wrow[j0 + jj];
            }
            __syncthreads();
            for (int jj = 0; jj < 128; jj++) {
                float cv = c[(size_t)(j0 + jj) * DK + d];
#pragma unroll
                for (int r = 0; r < 8; r++) acc[r] += Ws[r][jj] * cv;
            }
            __syncthreads();
        }
#pragma unroll
        for (int r = 0; r < 8; r++) {
            int gi = i0 + r;
            float bias = (gi < NC1) ? b1[gi] : b2[gi - NC1];
            g_cb[(size_t)(CB1_OFF + gi) * DK + d] = acc[r] + bias;
        }
    } else {
        int i = (blockIdx.x - 192) * 256 + threadIdx.x;
        if (i < NPTS * DK / 4) {
            float4 v = reinterpret_cast<const float4*>(x)[i];
            __nv_bfloat162* ph = reinterpret_cast<__nv_bfloat162*>(g_xh);
            ph[2*i]   = {__float2bfloat16(v.x), __float2bfloat16(v.y)};
            ph[2*i+1] = {__float2bfloat16(v.z), __float2bfloat16(v.w)};
        }
        if (i < NC0 * DK / 4)
            reinterpret_cast<float4*>(g_cb)[i] = reinterpret_cast<const float4*>(c)[i];
        if (i < MS_N) out[MS_OFF + i] = 0.0f;
        if (i < NC0)  g_used[i] = 0;
        if (i < 2)    g_loss[i] = 0.0f;
    }
}

// ---------------------------------------------------------------------------
// prep2: split codebooks to bf16 + halfnorms (one warp/row)              (#2)
// ---------------------------------------------------------------------------
__global__ __launch_bounds__(256) void k_prep2() {
    const int warp = (blockIdx.x * blockDim.x + threadIdx.x) >> 5;
    const int lane = threadIdx.x & 31;
    if (warp >= NCODES) return;
    const float4* row4 = reinterpret_cast<const float4*>(g_cb + (size_t)warp * DK);
    __nv_bfloat162* ch2 = reinterpret_cast<__nv_bfloat162*>(g_ch + (size_t)warp * DK);
    float s = 0.0f;
#pragma unroll
    for (int q = 0; q < 4; q++) {
        float4 v = row4[q * 32 + lane];
        s += v.x * v.x + v.y * v.y + v.z * v.z + v.w * v.w;
        ch2[(q * 32 + lane) * 2]     = {__float2bfloat16(v.x), __float2bfloat16(v.y)};
        ch2[(q * 32 + lane) * 2 + 1] = {__float2bfloat16(v.z), __float2bfloat16(v.w)};
    }
#pragma unroll
    for (int off = 16; off >= 1; off >>= 1) s += __shfl_xor_sync(0xffffffffu, s, off);
    if (lane == 0) g_halfnorm[warp] = 0.5f * s;
}

// ---------------------------------------------------------------------------
// HMMA approx GEMM (hh, K=512) + per-(row, 64-code half) top-2 emit.     (#3)
// CTA tile 128x128, 8 warps (4m x 2n), BK=64, 3-stage cp.async.
// ---------------------------------------------------------------------------
__device__ __forceinline__ void stage_chunk(int chunk, int stage, uint32_t sbase,
                                            int tid, int row0, int c0) {
    const int koff = chunk << 6;
    const uint32_t sA = sbase + (uint32_t)stage * 32768u;
    const uint32_t sB = sA + 16384u;
#pragma unroll
    for (int p = 0; p < 4; p++) {
        int idx = tid + (p << 8);
        int row = idx >> 3, cc = idx & 7;
        uint32_t sw = (uint32_t)((cc ^ (row & 7)) << 4);
        cp16(sA + (uint32_t)row * 128u + sw,
             g_xh + (size_t)(row0 + row) * DK + koff + cc * 8);
        cp16(sB + (uint32_t)row * 128u + sw,
             g_ch + (size_t)(c0 + row) * DK + koff + cc * 8);
    }
    CP_COMMIT();
}

__global__ __launch_bounds__(256) void k_mma() {
    extern __shared__ __align__(16) char smem[];
    __shared__ float hn_s[128];
    const uint32_t sbase = smem_u32(smem);
    const int tid  = threadIdx.x;
    const int lane = tid & 31;
    const int warp = tid >> 5;
    const int wm = warp >> 1;
    const int wn = warp & 1;
    const int c0   = blockIdx.x << 7;
    const int row0 = blockIdx.y << 7;

    if (tid < 128) hn_s[tid] = g_halfnorm[c0 + tid];

    float acc[2][8][4];
#pragma unroll
    for (int i = 0; i < 2; i++)
#pragma unroll
        for (int j = 0; j < 8; j++)
#pragma unroll
            for (int k = 0; k < 4; k++) acc[i][j][k] = 0.0f;

    stage_chunk(0, 0, sbase, tid, row0, c0);
    stage_chunk(1, 1, sbase, tid, row0, c0);

    const int rsel = lane & 15;
    const int ksel = lane >> 4;

    for (int chunk = 0; chunk < 8; chunk++) {
        const int stage = chunk % 3;
        if (chunk < 6) CP_WAIT(1); else CP_WAIT(0);
        __syncthreads();
        if (chunk + 2 < 8)
            stage_chunk(chunk + 2, (chunk + 2) % 3, sbase, tid, row0, c0);

        const uint32_t sA = sbase + (uint32_t)stage * 32768u;
        const uint32_t sB = sA + 16384u;
#pragma unroll
        for (int q = 0; q < 4; q++) {
            uint32_t a[2][4], b[4][4];
            const int csel = (q << 1) + ksel;
#pragma unroll
            for (int mf = 0; mf < 2; mf++) {
                int row = (wm << 5) + (mf << 4) + rsel;
                ldsm4(a[mf], sA + (uint32_t)row * 128u
                           + (uint32_t)((csel ^ (row & 7)) << 4));
            }
#pragma unroll
            for (int bt = 0; bt < 4; bt++) {
                int row = (wn << 6) + (bt << 4) + rsel;
                ldsm4(b[bt], sB + (uint32_t)row * 128u
                           + (uint32_t)((csel ^ (row & 7)) << 4));
            }
#pragma unroll
            for (int mf = 0; mf < 2; mf++)
#pragma unroll
                for (int bt = 0; bt < 4; bt++) {
                    mma_bf16(acc[mf][bt * 2],     a[mf], b[bt][0], b[bt][2]);
                    mma_bf16(acc[mf][bt * 2 + 1], a[mf], b[bt][1], b[bt][3]);
                }
        }
        __syncthreads();
    }

    // epilogue: per-row top-2 over this warp's 64-code half; direct global emit.
    // Half index within row = blockIdx.x * 2 + wn  (28 halves total).
    const int g = lane >> 2, t = lane & 3;
#pragma unroll
    for (int mf = 0; mf < 2; mf++) {
#pragma unroll
        for (int rh = 0; rh < 2; rh++) {
            const int row = (wm << 5) + (mf << 4) + (rh << 3) + g;
            unsigned long long b1 = ~0ULL, s1 = ~0ULL;
#pragma unroll
            for (int nf = 0; nf < 8; nf++) {
                int colb = (wn << 6) + (nf << 3) + (t << 1);
                float v0 = hn_s[colb]     - acc[mf][nf][rh * 2];
                float v1 = hn_s[colb + 1] - acc[mf][nf][rh * 2 + 1];
                unsigned long long p0 = ((unsigned long long)f2ord(v0) << 32)
                                      | (unsigned)(c0 + colb);
                unsigned long long p1 = ((unsigned long long)f2ord(v1) << 32)
                                      | (unsigned)(c0 + colb + 1);
                if (p0 < b1) { s1 = b1; b1 = p0; } else if (p0 < s1) s1 = p0;
                if (p1 < b1) { s1 = b1; b1 = p1; } else if (p1 < s1) s1 = p1;
            }
            // merge top-2 across the quad (t = lane bits 0-1)
#pragma unroll
            for (int off = 2; off >= 1; off >>= 1) {
                unsigned long long ob = __shfl_xor_sync(0xffffffffu, b1, off);
                unsigned long long os = __shfl_xor_sync(0xffffffffu, s1, off);
                if (ob < b1) { s1 = (b1 < os) ? b1 : os; b1 = ob; }
                else         { s1 = (ob < s1) ? ob : s1; }
            }
            if (t == 0)
                g_t2[(size_t)(row0 + row) * 28 + blockIdx.x * 2 + wn] =
                    make_ulonglong2(b1, s1);
        }
    }
}

// ---------------------------------------------------------------------------
// decide + gather: one WARP per row; no smem, no block syncs.            (#4)
// Halves: grp0 = [0,16), grp1 = [16,24), grp2 = [24,28).
// Global code base of half H is H<<6 (1024 = 16*64, 1536 = 24*64).
// ---------------------------------------------------------------------------
__global__ __launch_bounds__(256) void k_rg(const float* __restrict__ x,
                                            float* __restrict__ out) {
    const int w    = threadIdx.x >> 5;
    const int lane = threadIdx.x & 31;
    const int row  = blockIdx.x * 8 + w;

    float4 xv[4];
    const float4* xr4 = reinterpret_cast<const float4*>(x + (size_t)row * DK);
#pragma unroll
    for (int q = 0; q < 4; q++) xv[q] = xr4[q * 32 + lane];

    unsigned long long tb = ~0ULL, ts = ~0ULL;
    if (lane < 28) {
        ulonglong2 u = g_t2[(size_t)row * 28 + lane];
        tb = u.x; ts = u.y;
    }

    int zloc[3];

#pragma unroll
    for (int grp = 0; grp < 3; grp++) {
        const int t0 = (grp == 0) ? 0 : (grp == 1) ? 16 : 24;
        const int t1 = (grp == 0) ? 16 : (grp == 1) ? 24 : 28;
        const int gstart = (grp == 0) ? 0 : (grp == 1) ? CB1_OFF : CB2_OFF;
        const bool inr = (lane >= t0) && (lane < t1);

        unsigned long long b = inr ? tb : ~0ULL;
        unsigned long long best = b;
#pragma unroll
        for (int off = 16; off >= 1; off >>= 1) {
            unsigned long long o = __shfl_xor_sync(0xffffffffu, best, off);
            if (o < best) best = o;
        }
        const unsigned thr_ord = f2ord(ord2f((unsigned)(best >> 32)) + MARGIN);
        const unsigned long long thr_pack =
            ((unsigned long long)thr_ord << 32) | 0xffffffffULL;

        unsigned long long m = inr ? ((b == best) ? ts : b) : ~0ULL;
        unsigned long long second = m;
#pragma unroll
        for (int off = 16; off >= 1; off >>= 1) {
            unsigned long long o = __shfl_xor_sync(0xffffffffu, second, off);
            if (o < second) second = o;
        }

        if (second > thr_pack) {          // unambiguous: only best within margin
            zloc[grp] = (int)(best & 0xffffffffu) - gstart;
            continue;
        }

        // ambiguous: exact fp64 rescore (all loads warp-coalesced).
        double bs = 1e300; int bi = 0x7fffffff;
        const unsigned msk_s = __ballot_sync(0xffffffffu, inr && (ts <= thr_pack));
        unsigned msk_b = __ballot_sync(0xffffffffu, inr && (tb <= thr_pack)) & ~msk_s;

        while (msk_b) {                   // halves contributing only their best
            int L = __ffs(msk_b) - 1; msk_b &= msk_b - 1;
            int gi = (int)(__shfl_sync(0xffffffffu, tb, L) & 0xffffffffu);
            double sc = (double)g_halfnorm[gi] - wdot(xv, gi, lane);
            if (sc < bs || (sc == bs && gi < bi)) { bs = sc; bi = gi; }
        }
        unsigned mr = msk_s;              // halves needing full 64-code rescan
        while (mr) {
            int L = __ffs(mr) - 1; mr &= mr - 1;
            const int base = L << 6;
            for (int cc = 0; cc < 64; cc++) {
                int gi = base + cc;
                double sc = (double)g_halfnorm[gi] - wdot(xv, gi, lane);
                if (sc < bs || (sc == bs && gi < bi)) { bs = sc; bi = gi; }
            }
        }
        zloc[grp] = bi - gstart;
    }

    // gather + outputs + loss
    const int z  = zloc[0];
    const int z1 = zloc[1];
    const int z2 = zloc[2];
    if (lane == 0) g_used[z] = 1;

    const float4* m  = reinterpret_cast<const float4*>(&g_cb[(size_t)z * DK]);
    const float4* s1 = reinterpret_cast<const float4*>(&g_cb[(size_t)(CB1_OFF + z1) * DK]);
    const float4* s2 = reinterpret_cast<const float4*>(&g_cb[(size_t)(CB2_OFF + z2) * DK]);
    float4* om = reinterpret_cast<float4*>(&out[MAIN_OFF + (size_t)row * DK]);
    float4* os = reinterpret_cast<float4*>(&out[SUB_OFF + (size_t)row * DK]);

    float lm = 0.0f, ls = 0.0f;
#pragma unroll
    for (int q = 0; q < 4; q++) {
        int idx = q * 32 + lane;
        float4 mv = m[idx];
        float4 a  = s1[idx];
        float4 b  = s2[idx];
        float4 sv = make_float4(0.5f * (a.x + b.x), 0.5f * (a.y + b.y),
                                0.5f * (a.z + b.z), 0.5f * (a.w + b.w));
        om[idx] = mv;
        os[idx] = sv;
        float4 xq = xv[q];
        float dmx = mv.x - xq.x, dmy = mv.y - xq.y, dmz = mv.z - xq.z, dmw = mv.w - xq.w;
        float dsx = sv.x - xq.x, dsy = sv.y - xq.y, dsz = sv.z - xq.z, dsw = sv.w - xq.w;
        lm += dmx * dmx + dmy * dmy + dmz * dmz + dmw * dmw;
        ls += dsx * dsx + dsy * dsy + dsz * dsz + dsw * dsw;
    }
#pragma unroll
    for (int off = 16; off >= 1; off >>= 1) {
        lm += __shfl_xor_sync(0xffffffffu, lm, off);
        ls += __shfl_xor_sync(0xffffffffu, ls, off);
    }
    if (lane == 0) {
        atomicAdd(&g_loss[0], lm);
        atomicAdd(&g_loss[1], ls);
    }
}

// ---------------------------------------------------------------------------
__global__ void k_final(const int* __restrict__ training, float* __restrict__ out) {
    const int tid = threadIdx.x;
    int cnt = 0;
    for (int i = tid; i < NC0; i += 256) cnt += g_used[i];
#pragma unroll
    for (int off = 16; off >= 1; off >>= 1) cnt += __shfl_xor_sync(0xffffffffu, cnt, off);
    __shared__ int sc[8];
    int wid = tid >> 5, lane = tid & 31;
    if (lane == 0) sc[wid] = cnt;
    __syncthreads();
    if (tid == 0) {
        int total = 0;
#pragma unroll
        for (int w = 0; w < 8; w++) total += sc[w];
        float e_sum = g_loss[0] + g_loss[1];
        out[LOSS_OFF] = (*training != 0)
                      ? 1.25f * e_sum / ((float)NPTS * (float)DK) : 0.0f;
        out[UNIQ_OFF] = (float)total;
    }
}

// ---------------------------------------------------------------------------
extern "C" void kernel_launch(void* const* d_in, const int* in_sizes, int n_in,
                              void* d_out, int out_size) {
    const float* x  = (const float*)d_in[0];
    const float* c  = (const float*)d_in[1];
    const float* W1 = (const float*)d_in[2];
    const float* b1 = (const float*)d_in[3];
    const float* W2 = (const float*)d_in[4];
    const float* b2 = (const float*)d_in[5];
    const int* training = (const int*)d_in[6];
    float* out = (float*)d_out;

    const int MMA_SMEM = 3 * 32768;   // 96KB pipeline stages
    cudaFuncSetAttribute(k_mma, cudaFuncAttributeMaxDynamicSharedMemorySize, MMA_SMEM);

    k_front<<<192 + 16384, 256>>>(x, c, W1, b1, W2, b2, out);       // #1
    k_prep2<<<(NCODES * 32 + 255) / 256, 256>>>();                   // #2
    {
        dim3 g(NCODES / 128, NPTS / 128);   // (14, 256)
        k_mma<<<g, 256, MMA_SMEM>>>();                               // #3
    }
    k_rg<<<NPTS / 8, 256>>>(x, out);                                 // #4
    k_final<<<1, 256>>>(training, out);                              // #5
}

// round 13
// speedup vs baseline: 2.6983x; 1.6625x over previous
#include <cuda_runtime.h>
#include <cuda_bf16.h>
#include <cstdint>

// Problem constants
#define NPTS   32768
#define DK     512
#define NC0    1024
#define NC1    512
#define NC2    256
#define NCODES 1792
#define CB1_OFF 1024
#define CB2_OFF 1536

// out layout: main_out | sub_out | loss | ms_k_i(16x512 zeros) | unique
#define MAIN_OFF 0
#define SUB_OFF  (NPTS*DK)
#define LOSS_OFF (2*NPTS*DK)
#define MS_OFF   (LOSS_OFF + 1)
#define MS_N     (16*DK)
#define UNIQ_OFF (MS_OFF + MS_N)

#define MARGIN 2.0f   // empirically validated bound on 2x hh-approx score error

// Scratch (device globals; no allocation allowed)
__device__ float         g_cb[NCODES * DK];
__device__ float         g_halfnorm[NCODES];
__device__ float         g_losspart[1024];    // spread loss accumulators
__device__ int           g_used[NC0];
__device__ int4          g_z[NPTS];           // decided (z0, z1, z2, pad)
__device__ __nv_bfloat16 g_xh[NPTS * DK];
__device__ __nv_bfloat16 g_ch[NCODES * DK];
// per (row, 64-code half-tile) top-2 packed (scoreord<<32 | global_idx); 28 halves/row
__device__ ulonglong2    g_t2[(size_t)NPTS * 28];

__device__ __forceinline__ unsigned int f2ord(float f) {
    unsigned int u = __float_as_uint(f);
    return (u & 0x80000000u) ? ~u : (u | 0x80000000u);
}
__device__ __forceinline__ float ord2f(unsigned int u) {
    unsigned int v = (u & 0x80000000u) ? (u & 0x7fffffffu) : ~u;
    return __uint_as_float(v);
}
__device__ __forceinline__ uint32_t smem_u32(const void* p) {
    uint32_t a;
    asm("{ .reg .u64 t; cvta.to.shared.u64 t, %1; cvt.u32.u64 %0, t; }" : "=r"(a) : "l"(p));
    return a;
}
__device__ __forceinline__ void cp16(uint32_t dst, const void* src) {
    asm volatile("cp.async.cg.shared.global [%0], [%1], 16;" :: "r"(dst), "l"(src));
}
#define CP_COMMIT() asm volatile("cp.async.commit_group;" ::: "memory")
#define CP_WAIT(n)  asm volatile("cp.async.wait_group %0;" :: "n"(n) : "memory")

__device__ __forceinline__ void ldsm4(uint32_t* r, uint32_t addr) {
    asm volatile("ldmatrix.sync.aligned.m8n8.x4.shared.b16 {%0,%1,%2,%3}, [%4];"
        : "=r"(r[0]), "=r"(r[1]), "=r"(r[2]), "=r"(r[3]) : "r"(addr));
}
__device__ __forceinline__ void mma_bf16(float* d, const uint32_t* a,
                                         uint32_t b0, uint32_t b1) {
    asm volatile("mma.sync.aligned.m16n8k16.row.col.f32.bf16.bf16.f32 "
        "{%0,%1,%2,%3}, {%4,%5,%6,%7}, {%8,%9}, {%0,%1,%2,%3};"
        : "+f"(d[0]), "+f"(d[1]), "+f"(d[2]), "+f"(d[3])
        : "r"(a[0]), "r"(a[1]), "r"(a[2]), "r"(a[3]), "r"(b0), "r"(b1));
}

// coalesced warp-cooperative exact fp64 dot (x in registers, lane-strided)
__device__ __forceinline__ double wdot(const float4* xv, int gi, int lane) {
    const float4* cr4 = reinterpret_cast<const float4*>(g_cb + (size_t)gi * DK);
    double ds = 0.0;
#pragma unroll
    for (int q = 0; q < 4; q++) {
        float4 cv = cr4[q * 32 + lane];
        ds = fma((double)xv[q].x, (double)cv.x, ds);
        ds = fma((double)xv[q].y, (double)cv.y, ds);
        ds = fma((double)xv[q].z, (double)cv.z, ds);
        ds = fma((double)xv[q].w, (double)cv.w, ds);
    }
#pragma unroll
    for (int off = 16; off >= 1; off >>= 1)
        ds += __shfl_xor_sync(0xffffffffu, ds, off);
    return ds;
}

// ---------------------------------------------------------------------------
// front: blocks [0,192) = sub-codebook GEMM; rest = init+copy+split x.  (#1)
// ---------------------------------------------------------------------------
__global__ __launch_bounds__(256) void k_front(
    const float* __restrict__ x, const float* __restrict__ c,
    const float* __restrict__ W1, const float* __restrict__ b1,
    const float* __restrict__ W2, const float* __restrict__ b2,
    float* __restrict__ out)
{
    if (blockIdx.x < 192) {
        const int bx = blockIdx.x;
        const int i0 = (bx % 96) * 8;
        const int d  = (bx / 96) * 256 + threadIdx.x;
        __shared__ float Ws[8][128];
        float acc[8];
#pragma unroll
        for (int r = 0; r < 8; r++) acc[r] = 0.0f;
        for (int j0 = 0; j0 < NC0; j0 += 128) {
#pragma unroll
            for (int l = 0; l < 4; l++) {
                int p = threadIdx.x + l * 256;
                int r = p >> 7, jj = p & 127;
                int gi = i0 + r;
                const float* Wrow = (gi < NC1) ? &W1[(size_t)gi * NC0]
                                               : &W2[(size_t)(gi - NC1) * NC0];
                Ws[r][jj] = Wrow[j0 + jj];
            }
            __syncthreads();
            for (int jj = 0; jj < 128; jj++) {
                float cv = c[(size_t)(j0 + jj) * DK + d];
#pragma unroll
                for (int r = 0; r < 8; r++) acc[r] += Ws[r][jj] * cv;
            }
            __syncthreads();
        }
#pragma unroll
        for (int r = 0; r < 8; r++) {
            int gi = i0 + r;
            float bias = (gi < NC1) ? b1[gi] : b2[gi - NC1];
            g_cb[(size_t)(CB1_OFF + gi) * DK + d] = acc[r] + bias;
        }
    } else {
        int i = (blockIdx.x - 192) * 256 + threadIdx.x;
        if (i < NPTS * DK / 4) {
            float4 v = reinterpret_cast<const float4*>(x)[i];
            __nv_bfloat162* ph = reinterpret_cast<__nv_bfloat162*>(g_xh);
            ph[2*i]   = {__float2bfloat16(v.x), __float2bfloat16(v.y)};
            ph[2*i+1] = {__float2bfloat16(v.z), __float2bfloat16(v.w)};
        }
        if (i < NC0 * DK / 4)
            reinterpret_cast<float4*>(g_cb)[i] = reinterpret_cast<const float4*>(c)[i];
        if (i < MS_N)  out[MS_OFF + i] = 0.0f;
        if (i < NC0)   g_used[i] = 0;
        if (i < 1024)  g_losspart[i] = 0.0f;
    }
}

// ---------------------------------------------------------------------------
// prep2: split codebooks to bf16 + halfnorms (one warp/row)              (#2)
// ---------------------------------------------------------------------------
__global__ __launch_bounds__(256) void k_prep2() {
    const int warp = (blockIdx.x * blockDim.x + threadIdx.x) >> 5;
    const int lane = threadIdx.x & 31;
    if (warp >= NCODES) return;
    const float4* row4 = reinterpret_cast<const float4*>(g_cb + (size_t)warp * DK);
    __nv_bfloat162* ch2 = reinterpret_cast<__nv_bfloat162*>(g_ch + (size_t)warp * DK);
    float s = 0.0f;
#pragma unroll
    for (int q = 0; q < 4; q++) {
        float4 v = row4[q * 32 + lane];
        s += v.x * v.x + v.y * v.y + v.z * v.z + v.w * v.w;
        ch2[(q * 32 + lane) * 2]     = {__float2bfloat16(v.x), __float2bfloat16(v.y)};
        ch2[(q * 32 + lane) * 2 + 1] = {__float2bfloat16(v.z), __float2bfloat16(v.w)};
    }
#pragma unroll
    for (int off = 16; off >= 1; off >>= 1) s += __shfl_xor_sync(0xffffffffu, s, off);
    if (lane == 0) g_halfnorm[warp] = 0.5f * s;
}

// ---------------------------------------------------------------------------
// HMMA approx GEMM (hh, K=512) + per-(row, 64-code half) top-2 emit.     (#3)
// ---------------------------------------------------------------------------
__device__ __forceinline__ void stage_chunk(int chunk, int stage, uint32_t sbase,
                                            int tid, int row0, int c0) {
    const int koff = chunk << 6;
    const uint32_t sA = sbase + (uint32_t)stage * 32768u;
    const uint32_t sB = sA + 16384u;
#pragma unroll
    for (int p = 0; p < 4; p++) {
        int idx = tid + (p << 8);
        int row = idx >> 3, cc = idx & 7;
        uint32_t sw = (uint32_t)((cc ^ (row & 7)) << 4);
        cp16(sA + (uint32_t)row * 128u + sw,
             g_xh + (size_t)(row0 + row) * DK + koff + cc * 8);
        cp16(sB + (uint32_t)row * 128u + sw,
             g_ch + (size_t)(c0 + row) * DK + koff + cc * 8);
    }
    CP_COMMIT();
}

__global__ __launch_bounds__(256) void k_mma() {
    extern __shared__ __align__(16) char smem[];
    __shared__ float hn_s[128];
    const uint32_t sbase = smem_u32(smem);
    const int tid  = threadIdx.x;
    const int lane = tid & 31;
    const int warp = tid >> 5;
    const int wm = warp >> 1;
    const int wn = warp & 1;
    const int c0   = blockIdx.x << 7;
    const int row0 = blockIdx.y << 7;

    if (tid < 128) hn_s[tid] = g_halfnorm[c0 + tid];

    float acc[2][8][4];
#pragma unroll
    for (int i = 0; i < 2; i++)
#pragma unroll
        for (int j = 0; j < 8; j++)
#pragma unroll
            for (int k = 0; k < 4; k++) acc[i][j][k] = 0.0f;

    stage_chunk(0, 0, sbase, tid, row0, c0);
    stage_chunk(1, 1, sbase, tid, row0, c0);

    const int rsel = lane & 15;
    const int ksel = lane >> 4;

    for (int chunk = 0; chunk < 8; chunk++) {
        const int stage = chunk % 3;
        if (chunk < 6) CP_WAIT(1); else CP_WAIT(0);
        __syncthreads();
        if (chunk + 2 < 8)
            stage_chunk(chunk + 2, (chunk + 2) % 3, sbase, tid, row0, c0);

        const uint32_t sA = sbase + (uint32_t)stage * 32768u;
        const uint32_t sB = sA + 16384u;
#pragma unroll
        for (int q = 0; q < 4; q++) {
            uint32_t a[2][4], b[4][4];
            const int csel = (q << 1) + ksel;
#pragma unroll
            for (int mf = 0; mf < 2; mf++) {
                int row = (wm << 5) + (mf << 4) + rsel;
                ldsm4(a[mf], sA + (uint32_t)row * 128u
                           + (uint32_t)((csel ^ (row & 7)) << 4));
            }
#pragma unroll
            for (int bt = 0; bt < 4; bt++) {
                int row = (wn << 6) + (bt << 4) + rsel;
                ldsm4(b[bt], sB + (uint32_t)row * 128u
                           + (uint32_t)((csel ^ (row & 7)) << 4));
            }
#pragma unroll
            for (int mf = 0; mf < 2; mf++)
#pragma unroll
                for (int bt = 0; bt < 4; bt++) {
                    mma_bf16(acc[mf][bt * 2],     a[mf], b[bt][0], b[bt][2]);
                    mma_bf16(acc[mf][bt * 2 + 1], a[mf], b[bt][1], b[bt][3]);
                }
        }
        __syncthreads();
    }

    const int g = lane >> 2, t = lane & 3;
#pragma unroll
    for (int mf = 0; mf < 2; mf++) {
#pragma unroll
        for (int rh = 0; rh < 2; rh++) {
            const int row = (wm << 5) + (mf << 4) + (rh << 3) + g;
            unsigned long long b1 = ~0ULL, s1 = ~0ULL;
#pragma unroll
            for (int nf = 0; nf < 8; nf++) {
                int colb = (wn << 6) + (nf << 3) + (t << 1);
                float v0 = hn_s[colb]     - acc[mf][nf][rh * 2];
                float v1 = hn_s[colb + 1] - acc[mf][nf][rh * 2 + 1];
                unsigned long long p0 = ((unsigned long long)f2ord(v0) << 32)
                                      | (unsigned)(c0 + colb);
                unsigned long long p1 = ((unsigned long long)f2ord(v1) << 32)
                                      | (unsigned)(c0 + colb + 1);
                if (p0 < b1) { s1 = b1; b1 = p0; } else if (p0 < s1) s1 = p0;
                if (p1 < b1) { s1 = b1; b1 = p1; } else if (p1 < s1) s1 = p1;
            }
#pragma unroll
            for (int off = 2; off >= 1; off >>= 1) {
                unsigned long long ob = __shfl_xor_sync(0xffffffffu, b1, off);
                unsigned long long os = __shfl_xor_sync(0xffffffffu, s1, off);
                if (ob < b1) { s1 = (b1 < os) ? b1 : os; b1 = ob; }
                else         { s1 = (ob < s1) ? ob : s1; }
            }
            if (t == 0)
                g_t2[(size_t)(row0 + row) * 28 + blockIdx.x * 2 + wn] =
                    make_ulonglong2(b1, s1);
        }
    }
}

// ---------------------------------------------------------------------------
// decide: one WARP per row; reductions + rare exact fp64 rescue.         (#4)
// Writes g_z[row]. No gather here.
// ---------------------------------------------------------------------------
__global__ __launch_bounds__(256) void k_decide(const float* __restrict__ x) {
    __shared__ float xs[8][DK];
    const int w    = threadIdx.x >> 5;
    const int lane = threadIdx.x & 31;
    const int row  = blockIdx.x * 8 + w;

    unsigned long long tb = ~0ULL, ts = ~0ULL;
    if (lane < 28) {
        ulonglong2 u = g_t2[(size_t)row * 28 + lane];
        tb = u.x; ts = u.y;
    }

    bool xloaded = false;
    float4 xv[4];
    int zres[3];

#pragma unroll
    for (int grp = 0; grp < 3; grp++) {
        const int t0 = (grp == 0) ? 0 : (grp == 1) ? 16 : 24;
        const int t1 = (grp == 0) ? 16 : (grp == 1) ? 24 : 28;
        const int gstart = (grp == 0) ? 0 : (grp == 1) ? CB1_OFF : CB2_OFF;
        const bool inr = (lane >= t0) && (lane < t1);

        unsigned long long b = inr ? tb : ~0ULL;
        unsigned long long best = b;
#pragma unroll
        for (int off = 16; off >= 1; off >>= 1) {
            unsigned long long o = __shfl_xor_sync(0xffffffffu, best, off);
            if (o < best) best = o;
        }
        const unsigned thr_ord = f2ord(ord2f((unsigned)(best >> 32)) + MARGIN);
        const unsigned long long thr_pack =
            ((unsigned long long)thr_ord << 32) | 0xffffffffULL;

        unsigned long long m = inr ? ((b == best) ? ts : b) : ~0ULL;
        unsigned long long second = m;
#pragma unroll
        for (int off = 16; off >= 1; off >>= 1) {
            unsigned long long o = __shfl_xor_sync(0xffffffffu, second, off);
            if (o < second) second = o;
        }

        if (second > thr_pack) {
            zres[grp] = (int)(best & 0xffffffffu) - gstart;
            continue;
        }

        // ambiguous: exact fp64 rescore of candidates
        if (!xloaded) {
            const float4* xr4 = reinterpret_cast<const float4*>(x + (size_t)row * DK);
            float4* xs4 = reinterpret_cast<float4*>(xs[w]);
#pragma unroll
            for (int q = 0; q < 4; q++) {
                xv[q] = xr4[q * 32 + lane];
                xs4[q * 32 + lane] = xv[q];
            }
            xloaded = true;
        }
        __syncwarp();

        double bs = 1e300; int bi = 0x7fffffff;
        const unsigned msk_s = __ballot_sync(0xffffffffu, inr && (ts <= thr_pack));
        unsigned msk_b = __ballot_sync(0xffffffffu, inr && (tb <= thr_pack)) & ~msk_s;

        while (msk_b) {                 // halves contributing only their best
            int L = __ffs(msk_b) - 1; msk_b &= msk_b - 1;
            int gi = (int)(__shfl_sync(0xffffffffu, tb, L) & 0xffffffffu);
            double sc = (double)g_halfnorm[gi] - wdot(xv, gi, lane);
            if (sc < bs || (sc == bs && gi < bi)) { bs = sc; bi = gi; }
        }

        unsigned mr = msk_s;            // halves needing full 64-code rescan
        if (mr) {
            const int qid = lane >> 2, ql = lane & 3;
            const float4* xq4 = reinterpret_cast<const float4*>(xs[w] + ql * 128);
            while (mr) {
                int L = __ffs(mr) - 1; mr &= mr - 1;
                const int base = L << 6;
                for (int r8 = 0; r8 < 8; r8++) {
                    int gi = base + r8 * 8 + qid;       // quad per code
                    const float4* cr4 = reinterpret_cast<const float4*>(
                        g_cb + (size_t)gi * DK + ql * 128);
                    double d0 = 0.0, d1 = 0.0, d2 = 0.0, d3 = 0.0;
#pragma unroll
                    for (int j = 0; j < 32; j += 4) {
                        float4 c0v = cr4[j];
                        float4 c1v = cr4[j + 1];
                        float4 c2v = cr4[j + 2];
                        float4 c3v = cr4[j + 3];
                        float4 x0 = xq4[j];
                        float4 x1 = xq4[j + 1];
                        float4 x2 = xq4[j + 2];
                        float4 x3 = xq4[j + 3];
                        d0 = fma((double)x0.x, (double)c0v.x, d0);
                        d0 = fma((double)x0.y, (double)c0v.y, d0);
                        d0 = fma((double)x0.z, (double)c0v.z, d0);
                        d0 = fma((double)x0.w, (double)c0v.w, d0);
                        d1 = fma((double)x1.x, (double)c1v.x, d1);
                        d1 = fma((double)x1.y, (double)c1v.y, d1);
                        d1 = fma((double)x1.z, (double)c1v.z, d1);
                        d1 = fma((double)x1.w, (double)c1v.w, d1);
                        d2 = fma((double)x2.x, (double)c2v.x, d2);
                        d2 = fma((double)x2.y, (double)c2v.y, d2);
                        d2 = fma((double)x2.z, (double)c2v.z, d2);
                        d2 = fma((double)x2.w, (double)c2v.w, d2);
                        d3 = fma((double)x3.x, (double)c3v.x, d3);
                        d3 = fma((double)x3.y, (double)c3v.y, d3);
                        d3 = fma((double)x3.z, (double)c3v.z, d3);
                        d3 = fma((double)x3.w, (double)c3v.w, d3);
                    }
                    double ds = (d0 + d1) + (d2 + d3);
                    ds += __shfl_xor_sync(0xffffffffu, ds, 1);
                    ds += __shfl_xor_sync(0xffffffffu, ds, 2);
                    double sc = (double)g_halfnorm[gi] - ds;
                    if (sc < bs || (sc == bs && gi < bi)) { bs = sc; bi = gi; }
                }
            }
            // per-lane results -> warp-wide (score, idx) min
#pragma unroll
            for (int off = 16; off >= 1; off >>= 1) {
                double od = __shfl_xor_sync(0xffffffffu, bs, off);
                int    oi = __shfl_xor_sync(0xffffffffu, bi, off);
                if (od < bs || (od == bs && oi < bi)) { bs = od; bi = oi; }
            }
        }
        zres[grp] = bi - gstart;
    }

    if (lane == 0)
        g_z[row] = make_int4(zres[0], zres[1], zres[2], 0);
}

// ---------------------------------------------------------------------------
// gather: pure streaming; 2 rows per 256-thread block.                   (#5)
// ---------------------------------------------------------------------------
__global__ __launch_bounds__(256) void k_gather(const float* __restrict__ x,
                                                float* __restrict__ out) {
    const int half = threadIdx.x >> 7;
    const int tid  = threadIdx.x & 127;
    const int row  = blockIdx.x * 2 + half;

    int4 z = g_z[row];
    if (tid == 0) g_used[z.x] = 1;

    const float4* xr = reinterpret_cast<const float4*>(&x[(size_t)row * DK]);
    const float4* m  = reinterpret_cast<const float4*>(&g_cb[(size_t)z.x * DK]);
    const float4* s1 = reinterpret_cast<const float4*>(&g_cb[(size_t)(CB1_OFF + z.y) * DK]);
    const float4* s2 = reinterpret_cast<const float4*>(&g_cb[(size_t)(CB2_OFF + z.z) * DK]);
    float4* om = reinterpret_cast<float4*>(&out[MAIN_OFF + (size_t)row * DK]);
    float4* os = reinterpret_cast<float4*>(&out[SUB_OFF + (size_t)row * DK]);

    float4 xv = xr[tid];
    float4 mv = m[tid];
    float4 a  = s1[tid];
    float4 b  = s2[tid];
    float4 sv = make_float4(0.5f * (a.x + b.x), 0.5f * (a.y + b.y),
                            0.5f * (a.z + b.z), 0.5f * (a.w + b.w));
    om[tid] = mv;
    os[tid] = sv;

    float dmx = mv.x - xv.x, dmy = mv.y - xv.y, dmz = mv.z - xv.z, dmw = mv.w - xv.w;
    float dsx = sv.x - xv.x, dsy = sv.y - xv.y, dsz = sv.z - xv.z, dsw = sv.w - xv.w;
    float lm = dmx * dmx + dmy * dmy + dmz * dmz + dmw * dmw;
    float ls = dsx * dsx + dsy * dsy + dsz * dsz + dsw * dsw;

#pragma unroll
    for (int off = 16; off >= 1; off >>= 1) {
        lm += __shfl_xor_sync(0xffffffffu, lm, off);
        ls += __shfl_xor_sync(0xffffffffu, ls, off);
    }
    __shared__ float sm[8], ss[8];
    const int wid = threadIdx.x >> 5, lane = threadIdx.x & 31;
    if (lane == 0) { sm[wid] = lm; ss[wid] = ls; }
    __syncthreads();
    if (threadIdx.x == 0) {
        float tlm = 0.0f, tls = 0.0f;
#pragma unroll
        for (int i = 0; i < 8; i++) { tlm += sm[i]; tls += ss[i]; }
        const int slot = (blockIdx.x & 511) * 2;
        atomicAdd(&g_losspart[slot],     tlm);
        atomicAdd(&g_losspart[slot + 1], tls);
    }
}

// ---------------------------------------------------------------------------
__global__ void k_final(const int* __restrict__ training, float* __restrict__ out) {
    const int tid = threadIdx.x;   // 256
    int cnt = 0;
    for (int i = tid; i < NC0; i += 256) cnt += g_used[i];
    float e0 = 0.0f, e1 = 0.0f;
#pragma unroll
    for (int i = 0; i < 2; i++) {
        e0 += g_losspart[(tid + i * 256) * 2];
        e1 += g_losspart[(tid + i * 256) * 2 + 1];
    }
#pragma unroll
    for (int off = 16; off >= 1; off >>= 1) {
        cnt += __shfl_xor_sync(0xffffffffu, cnt, off);
        e0  += __shfl_xor_sync(0xffffffffu, e0, off);
        e1  += __shfl_xor_sync(0xffffffffu, e1, off);
    }
    __shared__ int   sc[8];
    __shared__ float s0[8], s1[8];
    int wid = tid >> 5, lane = tid & 31;
    if (lane == 0) { sc[wid] = cnt; s0[wid] = e0; s1[wid] = e1; }
    __syncthreads();
    if (tid == 0) {
        int total = 0; float t0 = 0.0f, t1 = 0.0f;
#pragma unroll
        for (int w = 0; w < 8; w++) { total += sc[w]; t0 += s0[w]; t1 += s1[w]; }
        out[LOSS_OFF] = (*training != 0)
                      ? 1.25f * (t0 + t1) / ((float)NPTS * (float)DK) : 0.0f;
        out[UNIQ_OFF] = (float)total;
    }
}

// ---------------------------------------------------------------------------
extern "C" void kernel_launch(void* const* d_in, const int* in_sizes, int n_in,
                              void* d_out, int out_size) {
    const float* x  = (const float*)d_in[0];
    const float* c  = (const float*)d_in[1];
    const float* W1 = (const float*)d_in[2];
    const float* b1 = (const float*)d_in[3];
    const float* W2 = (const float*)d_in[4];
    const float* b2 = (const float*)d_in[5];
    const int* training = (const int*)d_in[6];
    float* out = (float*)d_out;

    const int MMA_SMEM = 3 * 32768;   // 96KB pipeline stages
    cudaFuncSetAttribute(k_mma, cudaFuncAttributeMaxDynamicSharedMemorySize, MMA_SMEM);

    k_front<<<192 + 16384, 256>>>(x, c, W1, b1, W2, b2, out);       // #1
    k_prep2<<<(NCODES * 32 + 255) / 256, 256>>>();                   // #2
    {
        dim3 g(NCODES / 128, NPTS / 128);   // (14, 256)
        k_mma<<<g, 256, MMA_SMEM>>>();                               // #3
    }
    k_decide<<<NPTS / 8, 256>>>(x);                                  // #4
    k_gather<<<NPTS / 2, 256>>>(x, out);                             // #5
    k_final<<<1, 256>>>(training, out);                              // #6
}

// round 16
// speedup vs baseline: 6.7595x; 2.5051x over previous
#include <cuda_runtime.h>
#include <cuda_bf16.h>
#include <cstdint>

// Problem constants
#define NPTS   32768
#define DK     512
#define NC0    1024
#define NC1    512
#define NC2    256
#define NCODES 1792
#define CB1_OFF 1024
#define CB2_OFF 1536

// out layout: main_out | sub_out | loss | ms_k_i(16x512 zeros) | unique
#define MAIN_OFF 0
#define SUB_OFF  (NPTS*DK)
#define LOSS_OFF (2*NPTS*DK)
#define MS_OFF   (LOSS_OFF + 1)
#define MS_N     (16*DK)
#define UNIQ_OFF (MS_OFF + MS_N)

#define MARGIN 2.0f   // empirically validated bound on 2x hh-approx score error

// Scratch (device globals; no allocation allowed)
__device__ float         g_cb[NCODES * DK];
__device__ float         g_halfnorm[NCODES];
__device__ float         g_losspart[1024];    // spread loss accumulators
__device__ int           g_used[NC0];
__device__ int4          g_z[NPTS];           // decided (z0, z1, z2, pad)
__device__ __nv_bfloat16 g_xh[NPTS * DK];
__device__ __nv_bfloat16 g_ch[NCODES * DK];
// per (row, 64-code half-tile) top-2 packed (scoreord<<32 | global_idx); 28 halves/row
__device__ ulonglong2    g_t2[(size_t)NPTS * 28];

__device__ __forceinline__ unsigned int f2ord(float f) {
    unsigned int u = __float_as_uint(f);
    return (u & 0x80000000u) ? ~u : (u | 0x80000000u);
}
__device__ __forceinline__ float ord2f(unsigned int u) {
    unsigned int v = (u & 0x80000000u) ? (u & 0x7fffffffu) : ~u;
    return __uint_as_float(v);
}
__device__ __forceinline__ uint32_t smem_u32(const void* p) {
    uint32_t a;
    asm("{ .reg .u64 t; cvta.to.shared.u64 t, %1; cvt.u32.u64 %0, t; }" : "=r"(a) : "l"(p));
    return a;
}
__device__ __forceinline__ void cp16(uint32_t dst, const void* src) {
    asm volatile("cp.async.cg.shared.global [%0], [%1], 16;" :: "r"(dst), "l"(src));
}
#define CP_COMMIT() asm volatile("cp.async.commit_group;" ::: "memory")
#define CP_WAIT(n)  asm volatile("cp.async.wait_group %0;" :: "n"(n) : "memory")

__device__ __forceinline__ void ldsm4(uint32_t* r, uint32_t addr) {
    asm volatile("ldmatrix.sync.aligned.m8n8.x4.shared.b16 {%0,%1,%2,%3}, [%4];"
        : "=r"(r[0]), "=r"(r[1]), "=r"(r[2]), "=r"(r[3]) : "r"(addr));
}
__device__ __forceinline__ void mma_bf16(float* d, const uint32_t* a,
                                         uint32_t b0, uint32_t b1) {
    asm volatile("mma.sync.aligned.m16n8k16.row.col.f32.bf16.bf16.f32 "
        "{%0,%1,%2,%3}, {%4,%5,%6,%7}, {%8,%9}, {%0,%1,%2,%3};"
        : "+f"(d[0]), "+f"(d[1]), "+f"(d[2]), "+f"(d[3])
        : "r"(a[0]), "r"(a[1]), "r"(a[2]), "r"(a[3]), "r"(b0), "r"(b1));
}

// ---- exact-rounded fp32 ops via asm (immune to --use_fast_math reassociation)
__device__ __forceinline__ float fadd_rn(float a, float b) {
    float r; asm("add.rn.f32 %0,%1,%2;" : "=f"(r) : "f"(a), "f"(b)); return r;
}
__device__ __forceinline__ float fmul_rn(float a, float b) {
    float r; asm("mul.rn.f32 %0,%1,%2;" : "=f"(r) : "f"(a), "f"(b)); return r;
}
__device__ __forceinline__ float ffma_rn(float a, float b, float c) {
    float r; asm("fma.rn.f32 %0,%1,%2,%3;" : "=f"(r) : "f"(a), "f"(b), "f"(c)); return r;
}

// compensated accumulation of one product term: TwoProd + Kahan
// state: s (running sum), comp (Kahan carry), esum (product rounding errors)
#define KTERM(a_, b_) do {                                   \
    float p_ = fmul_rn((a_), (b_));                          \
    float e_ = ffma_rn((a_), (b_), -p_);                     \
    float y_ = fadd_rn(p_, -comp);                           \
    float t_ = fadd_rn(s, y_);                               \
    comp = fadd_rn(fadd_rn(t_, -s), -y_);                    \
    s = t_;                                                  \
    esum = fadd_rn(esum, e_);                                \
} while (0)

// warp-cooperative compensated fp32 dot (x in registers, lane-strided)
__device__ __forceinline__ float wdot_c32(const float4* xv, int gi, int lane) {
    const float4* cr4 = reinterpret_cast<const float4*>(g_cb + (size_t)gi * DK);
    float s = 0.0f, comp = 0.0f, esum = 0.0f;
#pragma unroll
    for (int q = 0; q < 4; q++) {
        float4 cv = cr4[q * 32 + lane];
        KTERM(xv[q].x, cv.x);
        KTERM(xv[q].y, cv.y);
        KTERM(xv[q].z, cv.z);
        KTERM(xv[q].w, cv.w);
    }
    float r = fadd_rn(s, esum);
#pragma unroll
    for (int off = 16; off >= 1; off >>= 1)
        r = fadd_rn(r, __shfl_xor_sync(0xffffffffu, r, off));
    return r;
}

// ---------------------------------------------------------------------------
// front: blocks [0,192) = sub-codebook GEMM; rest = init+copy+split x.  (#1)
// ---------------------------------------------------------------------------
__global__ __launch_bounds__(256) void k_front(
    const float* __restrict__ x, const float* __restrict__ c,
    const float* __restrict__ W1, const float* __restrict__ b1,
    const float* __restrict__ W2, const float* __restrict__ b2,
    float* __restrict__ out)
{
    if (blockIdx.x < 192) {
        const int bx = blockIdx.x;
        const int i0 = (bx % 96) * 8;
        const int d  = (bx / 96) * 256 + threadIdx.x;
        __shared__ float Ws[8][128];
        float acc[8];
#pragma unroll
        for (int r = 0; r < 8; r++) acc[r] = 0.0f;
        for (int j0 = 0; j0 < NC0; j0 += 128) {
#pragma unroll
            for (int l = 0; l < 4; l++) {
                int p = threadIdx.x + l * 256;
                int r = p >> 7, jj = p & 127;
                int gi = i0 + r;
                const float* Wrow = (gi < NC1) ? &W1[(size_t)gi * NC0]
                                               : &W2[(size_t)(gi - NC1) * NC0];
                Ws[r][jj] = Wrow[j0 + jj];
            }
            __syncthreads();
            for (int jj = 0; jj < 128; jj++) {
                float cv = c[(size_t)(j0 + jj) * DK + d];
#pragma unroll
                for (int r = 0; r < 8; r++) acc[r] += Ws[r][jj] * cv;
            }
            __syncthreads();
        }
#pragma unroll
        for (int r = 0; r < 8; r++) {
            int gi = i0 + r;
            float bias = (gi < NC1) ? b1[gi] : b2[gi - NC1];
            g_cb[(size_t)(CB1_OFF + gi) * DK + d] = acc[r] + bias;
        }
    } else {
        int i = (blockIdx.x - 192) * 256 + threadIdx.x;
        if (i < NPTS * DK / 4) {
            float4 v = reinterpret_cast<const float4*>(x)[i];
            __nv_bfloat162* ph = reinterpret_cast<__nv_bfloat162*>(g_xh);
            ph[2*i]   = {__float2bfloat16(v.x), __float2bfloat16(v.y)};
            ph[2*i+1] = {__float2bfloat16(v.z), __float2bfloat16(v.w)};
        }
        if (i < NC0 * DK / 4)
            reinterpret_cast<float4*>(g_cb)[i] = reinterpret_cast<const float4*>(c)[i];
        if (i < MS_N)  out[MS_OFF + i] = 0.0f;
        if (i < NC0)   g_used[i] = 0;
        if (i < 1024)  g_losspart[i] = 0.0f;
    }
}

// ---------------------------------------------------------------------------
// prep2: split codebooks to bf16 + halfnorms (one warp/row)              (#2)
// ---------------------------------------------------------------------------
__global__ __launch_bounds__(256) void k_prep2() {
    const int warp = (blockIdx.x * blockDim.x + threadIdx.x) >> 5;
    const int lane = threadIdx.x & 31;
    if (warp >= NCODES) return;
    const float4* row4 = reinterpret_cast<const float4*>(g_cb + (size_t)warp * DK);
    __nv_bfloat162* ch2 = reinterpret_cast<__nv_bfloat162*>(g_ch + (size_t)warp * DK);
    float s = 0.0f;
#pragma unroll
    for (int q = 0; q < 4; q++) {
        float4 v = row4[q * 32 + lane];
        s += v.x * v.x + v.y * v.y + v.z * v.z + v.w * v.w;
        ch2[(q * 32 + lane) * 2]     = {__float2bfloat16(v.x), __float2bfloat16(v.y)};
        ch2[(q * 32 + lane) * 2 + 1] = {__float2bfloat16(v.z), __float2bfloat16(v.w)};
    }
#pragma unroll
    for (int off = 16; off >= 1; off >>= 1) s += __shfl_xor_sync(0xffffffffu, s, off);
    if (lane == 0) g_halfnorm[warp] = 0.5f * s;
}

// ---------------------------------------------------------------------------
// HMMA approx GEMM (hh, K=512) + per-(row, 64-code half) top-2 emit.     (#3)
// ---------------------------------------------------------------------------
__device__ __forceinline__ void stage_chunk(int chunk, int stage, uint32_t sbase,
                                            int tid, int row0, int c0) {
    const int koff = chunk << 6;
    const uint32_t sA = sbase + (uint32_t)stage * 32768u;
    const uint32_t sB = sA + 16384u;
#pragma unroll
    for (int p = 0; p < 4; p++) {
        int idx = tid + (p << 8);
        int row = idx >> 3, cc = idx & 7;
        uint32_t sw = (uint32_t)((cc ^ (row & 7)) << 4);
        cp16(sA + (uint32_t)row * 128u + sw,
             g_xh + (size_t)(row0 + row) * DK + koff + cc * 8);
        cp16(sB + (uint32_t)row * 128u + sw,
             g_ch + (size_t)(c0 + row) * DK + koff + cc * 8);
    }
    CP_COMMIT();
}

__global__ __launch_bounds__(256) void k_mma() {
    extern __shared__ __align__(16) char smem[];
    __shared__ float hn_s[128];
    const uint32_t sbase = smem_u32(smem);
    const int tid  = threadIdx.x;
    const int lane = tid & 31;
    const int warp = tid >> 5;
    const int wm = warp >> 1;
    const int wn = warp & 1;
    const int c0   = blockIdx.x << 7;
    const int row0 = blockIdx.y << 7;

    if (tid < 128) hn_s[tid] = g_halfnorm[c0 + tid];

    float acc[2][8][4];
#pragma unroll
    for (int i = 0; i < 2; i++)
#pragma unroll
        for (int j = 0; j < 8; j++)
#pragma unroll
            for (int k = 0; k < 4; k++) acc[i][j][k] = 0.0f;

    stage_chunk(0, 0, sbase, tid, row0, c0);
    stage_chunk(1, 1, sbase, tid, row0, c0);

    const int rsel = lane & 15;
    const int ksel = lane >> 4;

    for (int chunk = 0; chunk < 8; chunk++) {
        const int stage = chunk % 3;
        if (chunk < 6) CP_WAIT(1); else CP_WAIT(0);
        __syncthreads();
        if (chunk + 2 < 8)
            stage_chunk(chunk + 2, (chunk + 2) % 3, sbase, tid, row0, c0);

        const uint32_t sA = sbase + (uint32_t)stage * 32768u;
        const uint32_t sB = sA + 16384u;
#pragma unroll
        for (int q = 0; q < 4; q++) {
            uint32_t a[2][4], b[4][4];
            const int csel = (q << 1) + ksel;
#pragma unroll
            for (int mf = 0; mf < 2; mf++) {
                int row = (wm << 5) + (mf << 4) + rsel;
                ldsm4(a[mf], sA + (uint32_t)row * 128u
                           + (uint32_t)((csel ^ (row & 7)) << 4));
            }
#pragma unroll
            for (int bt = 0; bt < 4; bt++) {
                int row = (wn << 6) + (bt << 4) + rsel;
                ldsm4(b[bt], sB + (uint32_t)row * 128u
                           + (uint32_t)((csel ^ (row & 7)) << 4));
            }
#pragma unroll
            for (int mf = 0; mf < 2; mf++)
#pragma unroll
                for (int bt = 0; bt < 4; bt++) {
                    mma_bf16(acc[mf][bt * 2],     a[mf], b[bt][0], b[bt][2]);
                    mma_bf16(acc[mf][bt * 2 + 1], a[mf], b[bt][1], b[bt][3]);
                }
        }
        __syncthreads();
    }

    const int g = lane >> 2, t = lane & 3;
#pragma unroll
    for (int mf = 0; mf < 2; mf++) {
#pragma unroll
        for (int rh = 0; rh < 2; rh++) {
            const int row = (wm << 5) + (mf << 4) + (rh << 3) + g;
            unsigned long long b1 = ~0ULL, s1 = ~0ULL;
#pragma unroll
            for (int nf = 0; nf < 8; nf++) {
                int colb = (wn << 6) + (nf << 3) + (t << 1);
                float v0 = hn_s[colb]     - acc[mf][nf][rh * 2];
                float v1 = hn_s[colb + 1] - acc[mf][nf][rh * 2 + 1];
                unsigned long long p0 = ((unsigned long long)f2ord(v0) << 32)
                                      | (unsigned)(c0 + colb);
                unsigned long long p1 = ((unsigned long long)f2ord(v1) << 32)
                                      | (unsigned)(c0 + colb + 1);
                if (p0 < b1) { s1 = b1; b1 = p0; } else if (p0 < s1) s1 = p0;
                if (p1 < b1) { s1 = b1; b1 = p1; } else if (p1 < s1) s1 = p1;
            }
#pragma unroll
            for (int off = 2; off >= 1; off >>= 1) {
                unsigned long long ob = __shfl_xor_sync(0xffffffffu, b1, off);
                unsigned long long os = __shfl_xor_sync(0xffffffffu, s1, off);
                if (ob < b1) { s1 = (b1 < os) ? b1 : os; b1 = ob; }
                else         { s1 = (ob < s1) ? ob : s1; }
            }
            if (t == 0)
                g_t2[(size_t)(row0 + row) * 28 + blockIdx.x * 2 + wn] =
                    make_ulonglong2(b1, s1);
        }
    }
}

// ---------------------------------------------------------------------------
// decide: one WARP per row; reductions + rare exact compensated-fp32 rescue.
// Writes g_z[row].                                                       (#4)
// ---------------------------------------------------------------------------
__global__ __launch_bounds__(256) void k_decide(const float* __restrict__ x) {
    __shared__ float xs[8][DK];
    const int w    = threadIdx.x >> 5;
    const int lane = threadIdx.x & 31;
    const int row  = blockIdx.x * 8 + w;

    unsigned long long tb = ~0ULL, ts = ~0ULL;
    if (lane < 28) {
        ulonglong2 u = g_t2[(size_t)row * 28 + lane];
        tb = u.x; ts = u.y;
    }

    bool xloaded = false;
    float4 xv[4];
    int zres[3];

#pragma unroll
    for (int grp = 0; grp < 3; grp++) {
        const int t0 = (grp == 0) ? 0 : (grp == 1) ? 16 : 24;
        const int t1 = (grp == 0) ? 16 : (grp == 1) ? 24 : 28;
        const int gstart = (grp == 0) ? 0 : (grp == 1) ? CB1_OFF : CB2_OFF;
        const bool inr = (lane >= t0) && (lane < t1);

        unsigned long long b = inr ? tb : ~0ULL;
        unsigned long long best = b;
#pragma unroll
        for (int off = 16; off >= 1; off >>= 1) {
            unsigned long long o = __shfl_xor_sync(0xffffffffu, best, off);
            if (o < best) best = o;
        }
        const unsigned thr_ord = f2ord(ord2f((unsigned)(best >> 32)) + MARGIN);
        const unsigned long long thr_pack =
            ((unsigned long long)thr_ord << 32) | 0xffffffffULL;

        unsigned long long m = inr ? ((b == best) ? ts : b) : ~0ULL;
        unsigned long long second = m;
#pragma unroll
        for (int off = 16; off >= 1; off >>= 1) {
            unsigned long long o = __shfl_xor_sync(0xffffffffu, second, off);
            if (o < second) second = o;
        }

        if (second > thr_pack) {
            zres[grp] = (int)(best & 0xffffffffu) - gstart;
            continue;
        }

        // ambiguous: exact compensated-fp32 rescore of candidates
        if (!xloaded) {
            const float4* xr4 = reinterpret_cast<const float4*>(x + (size_t)row * DK);
            float4* xs4 = reinterpret_cast<float4*>(xs[w]);
#pragma unroll
            for (int q = 0; q < 4; q++) {
                xv[q] = xr4[q * 32 + lane];
                xs4[q * 32 + lane] = xv[q];
            }
            xloaded = true;
        }
        __syncwarp();

        float bs = __int_as_float(0x7f7fffff);   // FLT_MAX
        int bi = 0x7fffffff;
        const unsigned msk_s = __ballot_sync(0xffffffffu, inr && (ts <= thr_pack));
        unsigned msk_b = __ballot_sync(0xffffffffu, inr && (tb <= thr_pack)) & ~msk_s;

        while (msk_b) {                 // halves contributing only their best
            int L = __ffs(msk_b) - 1; msk_b &= msk_b - 1;
            int gi = (int)(__shfl_sync(0xffffffffu, tb, L) & 0xffffffffu);
            float sc = fadd_rn(g_halfnorm[gi], -wdot_c32(xv, gi, lane));
            if (sc < bs || (sc == bs && gi < bi)) { bs = sc; bi = gi; }
        }

        unsigned mr = msk_s;            // halves needing full 64-code rescan
        if (mr) {
            const int qid = lane >> 2, ql = lane & 3;
            const float4* xq4 = reinterpret_cast<const float4*>(xs[w] + ql * 128);
            while (mr) {
                int L = __ffs(mr) - 1; mr &= mr - 1;
                const int base = L << 6;
                for (int r8 = 0; r8 < 8; r8++) {
                    int gi = base + r8 * 8 + qid;       // one code per quad
                    const float4* cr4 = reinterpret_cast<const float4*>(
                        g_cb + (size_t)gi * DK + ql * 128);
                    float s = 0.0f, comp = 0.0f, esum = 0.0f;
#pragma unroll
                    for (int j = 0; j < 32; j++) {
                        float4 cv = cr4[j];
                        float4 xq = xq4[j];
                        KTERM(xq.x, cv.x);
                        KTERM(xq.y, cv.y);
                        KTERM(xq.z, cv.z);
                        KTERM(xq.w, cv.w);
                    }
                    float ds = fadd_rn(s, esum);
                    ds = fadd_rn(ds, __shfl_xor_sync(0xffffffffu, ds, 1));
                    ds = fadd_rn(ds, __shfl_xor_sync(0xffffffffu, ds, 2));
                    float sc = fadd_rn(g_halfnorm[gi], -ds);
                    if (sc < bs || (sc == bs && gi < bi)) { bs = sc; bi = gi; }
                }
            }
            // per-lane results -> warp-wide (score, idx) min
#pragma unroll
            for (int off = 16; off >= 1; off >>= 1) {
                float od = __shfl_xor_sync(0xffffffffu, bs, off);
                int   oi = __shfl_xor_sync(0xffffffffu, bi, off);
                if (od < bs || (od == bs && oi < bi)) { bs = od; bi = oi; }
            }
        }
        zres[grp] = bi - gstart;
    }

    if (lane == 0)
        g_z[row] = make_int4(zres[0], zres[1], zres[2], 0);
}

// ---------------------------------------------------------------------------
// gather: pure streaming; 2 rows per 256-thread block.                   (#5)
// ---------------------------------------------------------------------------
__global__ __launch_bounds__(256) void k_gather(const float* __restrict__ x,
                                                float* __restrict__ out) {
    const int half = threadIdx.x >> 7;
    const int tid  = threadIdx.x & 127;
    const int row  = blockIdx.x * 2 + half;

    int4 z = g_z[row];
    if (tid == 0) g_used[z.x] = 1;

    const float4* xr = reinterpret_cast<const float4*>(&x[(size_t)row * DK]);
    const float4* m  = reinterpret_cast<const float4*>(&g_cb[(size_t)z.x * DK]);
    const float4* s1 = reinterpret_cast<const float4*>(&g_cb[(size_t)(CB1_OFF + z.y) * DK]);
    const float4* s2 = reinterpret_cast<const float4*>(&g_cb[(size_t)(CB2_OFF + z.z) * DK]);
    float4* om = reinterpret_cast<float4*>(&out[MAIN_OFF + (size_t)row * DK]);
    float4* os = reinterpret_cast<float4*>(&out[SUB_OFF + (size_t)row * DK]);

    float4 xv = xr[tid];
    float4 mv = m[tid];
    float4 a  = s1[tid];
    float4 b  = s2[tid];
    float4 sv = make_float4(0.5f * (a.x + b.x), 0.5f * (a.y + b.y),
                            0.5f * (a.z + b.z), 0.5f * (a.w + b.w));
    om[tid] = mv;
    os[tid] = sv;

    float dmx = mv.x - xv.x, dmy = mv.y - xv.y, dmz = mv.z - xv.z, dmw = mv.w - xv.w;
    float dsx = sv.x - xv.x, dsy = sv.y - xv.y, dsz = sv.z - xv.z, dsw = sv.w - xv.w;
    float lm = dmx * dmx + dmy * dmy + dmz * dmz + dmw * dmw;
    float ls = dsx * dsx + dsy * dsy + dsz * dsz + dsw * dsw;

#pragma unroll
    for (int off = 16; off >= 1; off >>= 1) {
        lm += __shfl_xor_sync(0xffffffffu, lm, off);
        ls += __shfl_xor_sync(0xffffffffu, ls, off);
    }
    __shared__ float sm[8], ss[8];
    const int wid = threadIdx.x >> 5, lane = threadIdx.x & 31;
    if (lane == 0) { sm[wid] = lm; ss[wid] = ls; }
    __syncthreads();
    if (threadIdx.x == 0) {
        float tlm = 0.0f, tls = 0.0f;
#pragma unroll
        for (int i = 0; i < 8; i++) { tlm += sm[i]; tls += ss[i]; }
        const int slot = (blockIdx.x & 511) * 2;
        atomicAdd(&g_losspart[slot],     tlm);
        atomicAdd(&g_losspart[slot + 1], tls);
    }
}

// ---------------------------------------------------------------------------
__global__ void k_final(const int* __restrict__ training, float* __restrict__ out) {
    const int tid = threadIdx.x;   // 256
    int cnt = 0;
    for (int i = tid; i < NC0; i += 256) cnt += g_used[i];
    float e0 = 0.0f, e1 = 0.0f;
#pragma unroll
    for (int i = 0; i < 2; i++) {
        e0 += g_losspart[(tid + i * 256) * 2];
        e1 += g_losspart[(tid + i * 256) * 2 + 1];
    }
#pragma unroll
    for (int off = 16; off >= 1; off >>= 1) {
        cnt += __shfl_xor_sync(0xffffffffu, cnt, off);
        e0  += __shfl_xor_sync(0xffffffffu, e0, off);
        e1  += __shfl_xor_sync(0xffffffffu, e1, off);
    }
    __shared__ int   sc[8];
    __shared__ float s0[8], s1[8];
    int wid = tid >> 5, lane = tid & 31;
    if (lane == 0) { sc[wid] = cnt; s0[wid] = e0; s1[wid] = e1; }
    __syncthreads();
    if (tid == 0) {
        int total = 0; float t0 = 0.0f, t1 = 0.0f;
#pragma unroll
        for (int w = 0; w < 8; w++) { total += sc[w]; t0 += s0[w]; t1 += s1[w]; }
        out[LOSS_OFF] = (*training != 0)
                      ? 1.25f * (t0 + t1) / ((float)NPTS * (float)DK) : 0.0f;
        out[UNIQ_OFF] = (float)total;
    }
}

// ---------------------------------------------------------------------------
extern "C" void kernel_launch(void* const* d_in, const int* in_sizes, int n_in,
                              void* d_out, int out_size) {
    const float* x  = (const float*)d_in[0];
    const float* c  = (const float*)d_in[1];
    const float* W1 = (const float*)d_in[2];
    const float* b1 = (const float*)d_in[3];
    const float* W2 = (const float*)d_in[4];
    const float* b2 = (const float*)d_in[5];
    const int* training = (const int*)d_in[6];
    float* out = (float*)d_out;

    const int MMA_SMEM = 3 * 32768;   // 96KB pipeline stages
    cudaFuncSetAttribute(k_mma, cudaFuncAttributeMaxDynamicSharedMemorySize, MMA_SMEM);

    k_front<<<192 + 16384, 256>>>(x, c, W1, b1, W2, b2, out);       // #1
    k_prep2<<<(NCODES * 32 + 255) / 256, 256>>>();                   // #2
    {
        dim3 g(NCODES / 128, NPTS / 128);   // (14, 256)
        k_mma<<<g, 256, MMA_SMEM>>>();                               // #3
    }
    k_decide<<<NPTS / 8, 256>>>(x);                                  // #4
    k_gather<<<NPTS / 2, 256>>>(x, out);                             // #5
    k_final<<<1, 256>>>(training, out);                              // #6
}

// round 17
// speedup vs baseline: 7.2704x; 1.0756x over previous
#include <cuda_runtime.h>
#include <cuda_bf16.h>
#include <cstdint>

// Problem constants
#define NPTS   32768
#define DK     512
#define NC0    1024
#define NC1    512
#define NC2    256
#define NCODES 1792
#define CB1_OFF 1024
#define CB2_OFF 1536

// out layout: main_out | sub_out | loss | ms_k_i(16x512 zeros) | unique
#define MAIN_OFF 0
#define SUB_OFF  (NPTS*DK)
#define LOSS_OFF (2*NPTS*DK)
#define MS_OFF   (LOSS_OFF + 1)
#define MS_N     (16*DK)
#define UNIQ_OFF (MS_OFF + MS_N)

#define MARGIN 2.0f   // empirically validated bound on 2x hh-approx score error

// Scratch (device globals; no allocation allowed)
__device__ float         g_cb[NCODES * DK];
__device__ float         g_halfnorm[NCODES];
__device__ float         g_losspart[1024];
__device__ int           g_used[NC0];
__device__ int           g_zarr[3 * NPTS];    // final local indices per (grp,row)
__device__ int           g_work[3 * NPTS];    // ambiguous worklist: row*4 | grp
__device__ int           g_nwork;
__device__ __nv_bfloat16 g_xh[NPTS * DK];
__device__ __nv_bfloat16 g_ch[NCODES * DK];
// per (row, 64-code half-tile) top-2 packed (scoreord<<32 | global_idx); 28 halves/row
__device__ ulonglong2    g_t2[(size_t)NPTS * 28];

__device__ __forceinline__ unsigned int f2ord(float f) {
    unsigned int u = __float_as_uint(f);
    return (u & 0x80000000u) ? ~u : (u | 0x80000000u);
}
__device__ __forceinline__ float ord2f(unsigned int u) {
    unsigned int v = (u & 0x80000000u) ? (u & 0x7fffffffu) : ~u;
    return __uint_as_float(v);
}
__device__ __forceinline__ uint32_t smem_u32(const void* p) {
    uint32_t a;
    asm("{ .reg .u64 t; cvta.to.shared.u64 t, %1; cvt.u32.u64 %0, t; }" : "=r"(a) : "l"(p));
    return a;
}
__device__ __forceinline__ void cp16(uint32_t dst, const void* src) {
    asm volatile("cp.async.cg.shared.global [%0], [%1], 16;" :: "r"(dst), "l"(src));
}
#define CP_COMMIT() asm volatile("cp.async.commit_group;" ::: "memory")
#define CP_WAIT(n)  asm volatile("cp.async.wait_group %0;" :: "n"(n) : "memory")

__device__ __forceinline__ void ldsm4(uint32_t* r, uint32_t addr) {
    asm volatile("ldmatrix.sync.aligned.m8n8.x4.shared.b16 {%0,%1,%2,%3}, [%4];"
        : "=r"(r[0]), "=r"(r[1]), "=r"(r[2]), "=r"(r[3]) : "r"(addr));
}
__device__ __forceinline__ void mma_bf16(float* d, const uint32_t* a,
                                         uint32_t b0, uint32_t b1) {
    asm volatile("mma.sync.aligned.m16n8k16.row.col.f32.bf16.bf16.f32 "
        "{%0,%1,%2,%3}, {%4,%5,%6,%7}, {%8,%9}, {%0,%1,%2,%3};"
        : "+f"(d[0]), "+f"(d[1]), "+f"(d[2]), "+f"(d[3])
        : "r"(a[0]), "r"(a[1]), "r"(a[2]), "r"(a[3]), "r"(b0), "r"(b1));
}

// ---- exact-rounded fp32 ops via asm (immune to --use_fast_math reassociation)
__device__ __forceinline__ float fadd_rn(float a, float b) {
    float r; asm("add.rn.f32 %0,%1,%2;" : "=f"(r) : "f"(a), "f"(b)); return r;
}
__device__ __forceinline__ float fmul_rn(float a, float b) {
    float r; asm("mul.rn.f32 %0,%1,%2;" : "=f"(r) : "f"(a), "f"(b)); return r;
}
__device__ __forceinline__ float ffma_rn(float a, float b, float c) {
    float r; asm("fma.rn.f32 %0,%1,%2,%3;" : "=f"(r) : "f"(a), "f"(b), "f"(c)); return r;
}

// compensated accumulation of one product term: TwoProd + Kahan
#define KTERM(a_, b_) do {                                   \
    float p_ = fmul_rn((a_), (b_));                          \
    float e_ = ffma_rn((a_), (b_), -p_);                     \
    float y_ = fadd_rn(p_, -comp);                           \
    float t_ = fadd_rn(s, y_);                               \
    comp = fadd_rn(fadd_rn(t_, -s), -y_);                    \
    s = t_;                                                  \
    esum = fadd_rn(esum, e_);                                \
} while (0)

// warp-cooperative compensated fp32 dot (x in registers, lane-strided)
__device__ __forceinline__ float wdot_c32(const float4* xv, int gi, int lane) {
    const float4* cr4 = reinterpret_cast<const float4*>(g_cb + (size_t)gi * DK);
    float s = 0.0f, comp = 0.0f, esum = 0.0f;
#pragma unroll
    for (int q = 0; q < 4; q++) {
        float4 cv = cr4[q * 32 + lane];
        KTERM(xv[q].x, cv.x);
        KTERM(xv[q].y, cv.y);
        KTERM(xv[q].z, cv.z);
        KTERM(xv[q].w, cv.w);
    }
    float r = fadd_rn(s, esum);
#pragma unroll
    for (int off = 16; off >= 1; off >>= 1)
        r = fadd_rn(r, __shfl_xor_sync(0xffffffffu, r, off));
    return r;
}

// ---------------------------------------------------------------------------
// front: blocks [0,192) = sub-codebook GEMM; rest = init+copy+split x.  (#1)
// ---------------------------------------------------------------------------
__global__ __launch_bounds__(256) void k_front(
    const float* __restrict__ x, const float* __restrict__ c,
    const float* __restrict__ W1, const float* __restrict__ b1,
    const float* __restrict__ W2, const float* __restrict__ b2,
    float* __restrict__ out)
{
    if (blockIdx.x < 192) {
        const int bx = blockIdx.x;
        const int i0 = (bx % 96) * 8;
        const int d  = (bx / 96) * 256 + threadIdx.x;
        __shared__ float Ws[8][128];
        float acc[8];
#pragma unroll
        for (int r = 0; r < 8; r++) acc[r] = 0.0f;
        for (int j0 = 0; j0 < NC0; j0 += 128) {
#pragma unroll
            for (int l = 0; l < 4; l++) {
                int p = threadIdx.x + l * 256;
                int r = p >> 7, jj = p & 127;
                int gi = i0 + r;
                const float* Wrow = (gi < NC1) ? &W1[(size_t)gi * NC0]
                                               : &W2[(size_t)(gi - NC1) * NC0];
                Ws[r][jj] = Wrow[j0 + jj];
            }
            __syncthreads();
            for (int jj = 0; jj < 128; jj++) {
                float cv = c[(size_t)(j0 + jj) * DK + d];
#pragma unroll
                for (int r = 0; r < 8; r++) acc[r] += Ws[r][jj] * cv;
            }
            __syncthreads();
        }
#pragma unroll
        for (int r = 0; r < 8; r++) {
            int gi = i0 + r;
            float bias = (gi < NC1) ? b1[gi] : b2[gi - NC1];
            g_cb[(size_t)(CB1_OFF + gi) * DK + d] = acc[r] + bias;
        }
    } else {
        int i = (blockIdx.x - 192) * 256 + threadIdx.x;
        if (i < NPTS * DK / 4) {
            float4 v = reinterpret_cast<const float4*>(x)[i];
            __nv_bfloat162* ph = reinterpret_cast<__nv_bfloat162*>(g_xh);
            ph[2*i]   = {__float2bfloat16(v.x), __float2bfloat16(v.y)};
            ph[2*i+1] = {__float2bfloat16(v.z), __float2bfloat16(v.w)};
        }
        if (i < NC0 * DK / 4)
            reinterpret_cast<float4*>(g_cb)[i] = reinterpret_cast<const float4*>(c)[i];
        if (i < MS_N)  out[MS_OFF + i] = 0.0f;
        if (i < NC0)   g_used[i] = 0;
        if (i < 1024)  g_losspart[i] = 0.0f;
        if (i == 0)    g_nwork = 0;
    }
}

// ---------------------------------------------------------------------------
// prep2: split codebooks to bf16 + halfnorms (one warp/row)              (#2)
// ---------------------------------------------------------------------------
__global__ __launch_bounds__(256) void k_prep2() {
    const int warp = (blockIdx.x * blockDim.x + threadIdx.x) >> 5;
    const int lane = threadIdx.x & 31;
    if (warp >= NCODES) return;
    const float4* row4 = reinterpret_cast<const float4*>(g_cb + (size_t)warp * DK);
    __nv_bfloat162* ch2 = reinterpret_cast<__nv_bfloat162*>(g_ch + (size_t)warp * DK);
    float s = 0.0f;
#pragma unroll
    for (int q = 0; q < 4; q++) {
        float4 v = row4[q * 32 + lane];
        s += v.x * v.x + v.y * v.y + v.z * v.z + v.w * v.w;
        ch2[(q * 32 + lane) * 2]     = {__float2bfloat16(v.x), __float2bfloat16(v.y)};
        ch2[(q * 32 + lane) * 2 + 1] = {__float2bfloat16(v.z), __float2bfloat16(v.w)};
    }
#pragma unroll
    for (int off = 16; off >= 1; off >>= 1) s += __shfl_xor_sync(0xffffffffu, s, off);
    if (lane == 0) g_halfnorm[warp] = 0.5f * s;
}

// ---------------------------------------------------------------------------
// HMMA approx GEMM (hh, K=512) + per-(row, 64-code half) top-2 emit.     (#3)
// ---------------------------------------------------------------------------
__device__ __forceinline__ void stage_chunk(int chunk, int stage, uint32_t sbase,
                                            int tid, int row0, int c0) {
    const int koff = chunk << 6;
    const uint32_t sA = sbase + (uint32_t)stage * 32768u;
    const uint32_t sB = sA + 16384u;
#pragma unroll
    for (int p = 0; p < 4; p++) {
        int idx = tid + (p << 8);
        int row = idx >> 3, cc = idx & 7;
        uint32_t sw = (uint32_t)((cc ^ (row & 7)) << 4);
        cp16(sA + (uint32_t)row * 128u + sw,
             g_xh + (size_t)(row0 + row) * DK + koff + cc * 8);
        cp16(sB + (uint32_t)row * 128u + sw,
             g_ch + (size_t)(c0 + row) * DK + koff + cc * 8);
    }
    CP_COMMIT();
}

__global__ __launch_bounds__(256) void k_mma() {
    extern __shared__ __align__(16) char smem[];
    __shared__ float hn_s[128];
    const uint32_t sbase = smem_u32(smem);
    const int tid  = threadIdx.x;
    const int lane = tid & 31;
    const int warp = tid >> 5;
    const int wm = warp >> 1;
    const int wn = warp & 1;
    const int c0   = blockIdx.x << 7;
    const int row0 = blockIdx.y << 7;

    if (tid < 128) hn_s[tid] = g_halfnorm[c0 + tid];

    float acc[2][8][4];
#pragma unroll
    for (int i = 0; i < 2; i++)
#pragma unroll
        for (int j = 0; j < 8; j++)
#pragma unroll
            for (int k = 0; k < 4; k++) acc[i][j][k] = 0.0f;

    stage_chunk(0, 0, sbase, tid, row0, c0);
    stage_chunk(1, 1, sbase, tid, row0, c0);

    const int rsel = lane & 15;
    const int ksel = lane >> 4;

    for (int chunk = 0; chunk < 8; chunk++) {
        const int stage = chunk % 3;
        if (chunk < 6) CP_WAIT(1); else CP_WAIT(0);
        __syncthreads();
        if (chunk + 2 < 8)
            stage_chunk(chunk + 2, (chunk + 2) % 3, sbase, tid, row0, c0);

        const uint32_t sA = sbase + (uint32_t)stage * 32768u;
        const uint32_t sB = sA + 16384u;
#pragma unroll
        for (int q = 0; q < 4; q++) {
            uint32_t a[2][4], b[4][4];
            const int csel = (q << 1) + ksel;
#pragma unroll
            for (int mf = 0; mf < 2; mf++) {
                int row = (wm << 5) + (mf << 4) + rsel;
                ldsm4(a[mf], sA + (uint32_t)row * 128u
                           + (uint32_t)((csel ^ (row & 7)) << 4));
            }
#pragma unroll
            for (int bt = 0; bt < 4; bt++) {
                int row = (wn << 6) + (bt << 4) + rsel;
                ldsm4(b[bt], sB + (uint32_t)row * 128u
                           + (uint32_t)((csel ^ (row & 7)) << 4));
            }
#pragma unroll
            for (int mf = 0; mf < 2; mf++)
#pragma unroll
                for (int bt = 0; bt < 4; bt++) {
                    mma_bf16(acc[mf][bt * 2],     a[mf], b[bt][0], b[bt][2]);
                    mma_bf16(acc[mf][bt * 2 + 1], a[mf], b[bt][1], b[bt][3]);
                }
        }
        __syncthreads();
    }

    const int g = lane >> 2, t = lane & 3;
#pragma unroll
    for (int mf = 0; mf < 2; mf++) {
#pragma unroll
        for (int rh = 0; rh < 2; rh++) {
            const int row = (wm << 5) + (mf << 4) + (rh << 3) + g;
            unsigned long long b1 = ~0ULL, s1 = ~0ULL;
#pragma unroll
            for (int nf = 0; nf < 8; nf++) {
                int colb = (wn << 6) + (nf << 3) + (t << 1);
                float v0 = hn_s[colb]     - acc[mf][nf][rh * 2];
                float v1 = hn_s[colb + 1] - acc[mf][nf][rh * 2 + 1];
                unsigned long long p0 = ((unsigned long long)f2ord(v0) << 32)
                                      | (unsigned)(c0 + colb);
                unsigned long long p1 = ((unsigned long long)f2ord(v1) << 32)
                                      | (unsigned)(c0 + colb + 1);
                if (p0 < b1) { s1 = b1; b1 = p0; } else if (p0 < s1) s1 = p0;
                if (p1 < b1) { s1 = b1; b1 = p1; } else if (p1 < s1) s1 = p1;
            }
#pragma unroll
            for (int off = 2; off >= 1; off >>= 1) {
                unsigned long long ob = __shfl_xor_sync(0xffffffffu, b1, off);
                unsigned long long os = __shfl_xor_sync(0xffffffffu, s1, off);
                if (ob < b1) { s1 = (b1 < os) ? b1 : os; b1 = ob; }
                else         { s1 = (ob < s1) ? ob : s1; }
            }
            if (t == 0)
                g_t2[(size_t)(row0 + row) * 28 + blockIdx.x * 2 + wn] =
                    make_ulonglong2(b1, s1);
        }
    }
}

// ---------------------------------------------------------------------------
// decide (CHEAP): one WARP per row; reductions only. Ambiguous (row,grp)
// go to the worklist; decided indices written directly.                  (#4)
// ---------------------------------------------------------------------------
__global__ __launch_bounds__(256) void k_decide() {
    const int w    = threadIdx.x >> 5;
    const int lane = threadIdx.x & 31;
    const int row  = blockIdx.x * 8 + w;

    unsigned long long tb = ~0ULL, ts = ~0ULL;
    if (lane < 28) {
        ulonglong2 u = g_t2[(size_t)row * 28 + lane];
        tb = u.x; ts = u.y;
    }

#pragma unroll
    for (int grp = 0; grp < 3; grp++) {
        const int t0 = (grp == 0) ? 0 : (grp == 1) ? 16 : 24;
        const int t1 = (grp == 0) ? 16 : (grp == 1) ? 24 : 28;
        const int gstart = (grp == 0) ? 0 : (grp == 1) ? CB1_OFF : CB2_OFF;
        const bool inr = (lane >= t0) && (lane < t1);

        unsigned long long b = inr ? tb : ~0ULL;
        unsigned long long best = b;
#pragma unroll
        for (int off = 16; off >= 1; off >>= 1) {
            unsigned long long o = __shfl_xor_sync(0xffffffffu, best, off);
            if (o < best) best = o;
        }
        const unsigned thr_ord = f2ord(ord2f((unsigned)(best >> 32)) + MARGIN);
        const unsigned long long thr_pack =
            ((unsigned long long)thr_ord << 32) | 0xffffffffULL;

        unsigned long long m = inr ? ((b == best) ? ts : b) : ~0ULL;
        unsigned long long second = m;
#pragma unroll
        for (int off = 16; off >= 1; off >>= 1) {
            unsigned long long o = __shfl_xor_sync(0xffffffffu, second, off);
            if (o < second) second = o;
        }

        if (lane == 0) {
            if (second > thr_pack) {
                g_zarr[grp * NPTS + row] = (int)(best & 0xffffffffu) - gstart;
            } else {
                int idx = atomicAdd(&g_nwork, 1);
                g_work[idx] = (row << 2) | grp;
            }
        }
    }
}

// ---------------------------------------------------------------------------
// rescue: grid-stride over worklist; one warp per ambiguous (row,grp).   (#5)
// Exact compensated-fp32 rescore of candidates within margin.
// ---------------------------------------------------------------------------
__global__ __launch_bounds__(256, 2) void k_rescue(const float* __restrict__ x) {
    __shared__ float xs[8][DK];
    const int w    = threadIdx.x >> 5;
    const int lane = threadIdx.x & 31;
    const int gw   = blockIdx.x * 8 + w;
    const int nwarps = gridDim.x * 8;
    const int n = g_nwork;

    for (int e = gw; e < n; e += nwarps) {
        const int ent = g_work[e];
        const int row = ent >> 2;
        const int grp = ent & 3;
        const int t0 = (grp == 0) ? 0 : (grp == 1) ? 16 : 24;
        const int t1 = (grp == 0) ? 16 : (grp == 1) ? 24 : 28;
        const int gstart = (grp == 0) ? 0 : (grp == 1) ? CB1_OFF : CB2_OFF;
        const int nh = t1 - t0;

        unsigned long long tb = ~0ULL, ts = ~0ULL;
        if (lane < nh) {
            ulonglong2 u = g_t2[(size_t)row * 28 + t0 + lane];
            tb = u.x; ts = u.y;
        }
        unsigned long long best = tb;
#pragma unroll
        for (int off = 16; off >= 1; off >>= 1) {
            unsigned long long o = __shfl_xor_sync(0xffffffffu, best, off);
            if (o < best) best = o;
        }
        const unsigned thr_ord = f2ord(ord2f((unsigned)(best >> 32)) + MARGIN);
        const unsigned long long thr_pack =
            ((unsigned long long)thr_ord << 32) | 0xffffffffULL;

        // stage x row (registers + smem for quad path)
        float4 xv[4];
        const float4* xr4 = reinterpret_cast<const float4*>(x + (size_t)row * DK);
        float4* xs4 = reinterpret_cast<float4*>(xs[w]);
#pragma unroll
        for (int q = 0; q < 4; q++) {
            xv[q] = xr4[q * 32 + lane];
            xs4[q * 32 + lane] = xv[q];
        }
        __syncwarp();

        float bs = __int_as_float(0x7f7fffff);
        int bi = 0x7fffffff;
        const unsigned msk_s =
            __ballot_sync(0xffffffffu, (lane < nh) && (ts <= thr_pack));
        unsigned msk_b =
            __ballot_sync(0xffffffffu, (lane < nh) && (tb <= thr_pack)) & ~msk_s;

        while (msk_b) {               // halves contributing only their best
            int L = __ffs(msk_b) - 1; msk_b &= msk_b - 1;
            int gi = (int)(__shfl_sync(0xffffffffu, tb, L) & 0xffffffffu);
            float sc = fadd_rn(g_halfnorm[gi], -wdot_c32(xv, gi, lane));
            if (sc < bs || (sc == bs && gi < bi)) { bs = sc; bi = gi; }
        }

        unsigned mr = msk_s;          // halves needing full 64-code rescan
        if (mr) {
            const int qid = lane >> 2, ql = lane & 3;
            const float4* xq4 = reinterpret_cast<const float4*>(xs[w] + ql * 128);
            while (mr) {
                int L = __ffs(mr) - 1; mr &= mr - 1;
                const int base = (t0 + L) << 6;
                for (int r8 = 0; r8 < 8; r8++) {
                    int gi = base + r8 * 8 + qid;     // one code per quad
                    const float4* cr4 = reinterpret_cast<const float4*>(
                        g_cb + (size_t)gi * DK + ql * 128);
                    float s = 0.0f, comp = 0.0f, esum = 0.0f;
#pragma unroll 8
                    for (int j = 0; j < 32; j++) {
                        float4 cv = cr4[j];
                        float4 xq = xq4[j];
                        KTERM(xq.x, cv.x);
                        KTERM(xq.y, cv.y);
                        KTERM(xq.z, cv.z);
                        KTERM(xq.w, cv.w);
                    }
                    float ds = fadd_rn(s, esum);
                    ds = fadd_rn(ds, __shfl_xor_sync(0xffffffffu, ds, 1));
                    ds = fadd_rn(ds, __shfl_xor_sync(0xffffffffu, ds, 2));
                    float sc = fadd_rn(g_halfnorm[gi], -ds);
                    if (sc < bs || (sc == bs && gi < bi)) { bs = sc; bi = gi; }
                }
            }
#pragma unroll
            for (int off = 16; off >= 1; off >>= 1) {
                float od = __shfl_xor_sync(0xffffffffu, bs, off);
                int   oi = __shfl_xor_sync(0xffffffffu, bi, off);
                if (od < bs || (od == bs && oi < bi)) { bs = od; bi = oi; }
            }
        }
        if (lane == 0)
            g_zarr[grp * NPTS + row] = bi - gstart;
        __syncwarp();
    }
}

// ---------------------------------------------------------------------------
// gather: pure streaming; 2 rows per 256-thread block.                   (#6)
// ---------------------------------------------------------------------------
__global__ __launch_bounds__(256) void k_gather(const float* __restrict__ x,
                                                float* __restrict__ out) {
    const int half = threadIdx.x >> 7;
    const int tid  = threadIdx.x & 127;
    const int row  = blockIdx.x * 2 + half;

    const int z0 = g_zarr[row];
    const int z1 = g_zarr[NPTS + row];
    const int z2 = g_zarr[2 * NPTS + row];
    if (tid == 0) g_used[z0] = 1;

    const float4* xr = reinterpret_cast<const float4*>(&x[(size_t)row * DK]);
    const float4* m  = reinterpret_cast<const float4*>(&g_cb[(size_t)z0 * DK]);
    const float4* s1 = reinterpret_cast<const float4*>(&g_cb[(size_t)(CB1_OFF + z1) * DK]);
    const float4* s2 = reinterpret_cast<const float4*>(&g_cb[(size_t)(CB2_OFF + z2) * DK]);
    float4* om = reinterpret_cast<float4*>(&out[MAIN_OFF + (size_t)row * DK]);
    float4* os = reinterpret_cast<float4*>(&out[SUB_OFF + (size_t)row * DK]);

    float4 xv = xr[tid];
    float4 mv = m[tid];
    float4 a  = s1[tid];
    float4 b  = s2[tid];
    float4 sv = make_float4(0.5f * (a.x + b.x), 0.5f * (a.y + b.y),
                            0.5f * (a.z + b.z), 0.5f * (a.w + b.w));
    om[tid] = mv;
    os[tid] = sv;

    float dmx = mv.x - xv.x, dmy = mv.y - xv.y, dmz = mv.z - xv.z, dmw = mv.w - xv.w;
    float dsx = sv.x - xv.x, dsy = sv.y - xv.y, dsz = sv.z - xv.z, dsw = sv.w - xv.w;
    float lm = dmx * dmx + dmy * dmy + dmz * dmz + dmw * dmw;
    float ls = dsx * dsx + dsy * dsy + dsz * dsz + dsw * dsw;

#pragma unroll
    for (int off = 16; off >= 1; off >>= 1) {
        lm += __shfl_xor_sync(0xffffffffu, lm, off);
        ls += __shfl_xor_sync(0xffffffffu, ls, off);
    }
    __shared__ float sm[8], ss[8];
    const int wid = threadIdx.x >> 5, lane = threadIdx.x & 31;
    if (lane == 0) { sm[wid] = lm; ss[wid] = ls; }
    __syncthreads();
    if (threadIdx.x == 0) {
        float tlm = 0.0f, tls = 0.0f;
#pragma unroll
        for (int i = 0; i < 8; i++) { tlm += sm[i]; tls += ss[i]; }
        const int slot = (blockIdx.x & 511) * 2;
        atomicAdd(&g_losspart[slot],     tlm);
        atomicAdd(&g_losspart[slot + 1], tls);
    }
}

// ---------------------------------------------------------------------------
__global__ void k_final(const int* __restrict__ training, float* __restrict__ out) {
    const int tid = threadIdx.x;   // 256
    int cnt = 0;
    for (int i = tid; i < NC0; i += 256) cnt += g_used[i];
    float e0 = 0.0f, e1 = 0.0f;
#pragma unroll
    for (int i = 0; i < 2; i++) {
        e0 += g_losspart[(tid + i * 256) * 2];
        e1 += g_losspart[(tid + i * 256) * 2 + 1];
    }
#pragma unroll
    for (int off = 16; off >= 1; off >>= 1) {
        cnt += __shfl_xor_sync(0xffffffffu, cnt, off);
        e0  += __shfl_xor_sync(0xffffffffu, e0, off);
        e1  += __shfl_xor_sync(0xffffffffu, e1, off);
    }
    __shared__ int   sc[8];
    __shared__ float s0[8], s1[8];
    int wid = tid >> 5, lane = tid & 31;
    if (lane == 0) { sc[wid] = cnt; s0[wid] = e0; s1[wid] = e1; }
    __syncthreads();
    if (tid == 0) {
        int total = 0; float t0 = 0.0f, t1 = 0.0f;
#pragma unroll
        for (int w = 0; w < 8; w++) { total += sc[w]; t0 += s0[w]; t1 += s1[w]; }
        out[LOSS_OFF] = (*training != 0)
                      ? 1.25f * (t0 + t1) / ((float)NPTS * (float)DK) : 0.0f;
        out[UNIQ_OFF] = (float)total;
    }
}

// ---------------------------------------------------------------------------
extern "C" void kernel_launch(void* const* d_in, const int* in_sizes, int n_in,
                              void* d_out, int out_size) {
    const float* x  = (const float*)d_in[0];
    const float* c  = (const float*)d_in[1];
    const float* W1 = (const float*)d_in[2];
    const float* b1 = (const float*)d_in[3];
    const float* W2 = (const float*)d_in[4];
    const float* b2 = (const float*)d_in[5];
    const int* training = (const int*)d_in[6];
    float* out = (float*)d_out;

    const int MMA_SMEM = 3 * 32768;   // 96KB pipeline stages
    cudaFuncSetAttribute(k_mma, cudaFuncAttributeMaxDynamicSharedMemorySize, MMA_SMEM);

    k_front<<<192 + 16384, 256>>>(x, c, W1, b1, W2, b2, out);       // #1
    k_prep2<<<(NCODES * 32 + 255) / 256, 256>>>();                   // #2
    {
        dim3 g(NCODES / 128, NPTS / 128);   // (14, 256)
        k_mma<<<g, 256, MMA_SMEM>>>();                               // #3
    }
    k_decide<<<NPTS / 8, 256>>>();                                   // #4
    k_rescue<<<512, 256>>>(x);                                       // #5
    k_gather<<<NPTS / 2, 256>>>(x, out);                             // #6
    k_final<<<1, 256>>>(training, out);                              // #7
}